// round 6
// baseline (speedup 1.0000x reference)
#include <cuda_runtime.h>
#include <math.h>

#define NB   2
#define NS   4096
#define NE   2560
#define NH   8
#define NKV  4
#define ND   256
#define NWIN 1024

// ---------------- scratch (device globals: allocation-free) ----------------
static __device__ float g_qkv[(size_t)NB * NS * (NH + 2 * NKV) * ND]; // [8192, 4096]
static __device__ float g_q  [(size_t)NB * NH  * NS * ND];  // tf32 bits
static __device__ float g_k  [(size_t)NB * NKV * NS * ND];  // tf32 bits
static __device__ float g_v  [(size_t)NB * NKV * NS * ND];  // tf32 bits
static __device__ float g_att[(size_t)NB * NS * NH * ND];   // fp32

__device__ __forceinline__ unsigned f2tf32(float f) {
    unsigned u;
    asm volatile("cvt.rna.tf32.f32 %0, %1;" : "=r"(u) : "f"(f));
    return u;
}

__device__ __forceinline__ void mma_tf32(float* d,
        unsigned a0, unsigned a1, unsigned a2, unsigned a3,
        unsigned b0, unsigned b1) {
    asm volatile(
        "mma.sync.aligned.m16n8k8.row.col.f32.tf32.tf32.f32 "
        "{%0,%1,%2,%3},{%4,%5,%6,%7},{%8,%9},{%0,%1,%2,%3};"
        : "+f"(d[0]), "+f"(d[1]), "+f"(d[2]), "+f"(d[3])
        : "r"(a0), "r"(a1), "r"(a2), "r"(a3), "r"(b0), "r"(b1));
}

__device__ __forceinline__ void cp16(unsigned smem_addr, const void* gptr) {
    asm volatile("cp.async.cg.shared.global [%0], [%1], 16;"
                 :: "r"(smem_addr), "l"(gptr));
}

// ---------------------------------------------------------------------------
// TF32 tensor-core GEMM: C[M,N] = A[M,K] @ B[N,K]^T  (round-3 proven config)
// 128x128 tile, BK=32, 256 threads (8 warps, 64x32 each).
// ---------------------------------------------------------------------------
#define SPITCH 36

__global__ __launch_bounds__(256, 1) void tf32gemm_nt(
        const float* __restrict__ A, const float* __restrict__ Bm,
        float* __restrict__ C, int M, int N, int K)
{
    __shared__ unsigned As[128 * SPITCH];
    __shared__ unsigned Bs[128 * SPITCH];

    int tid  = threadIdx.x;
    int lane = tid & 31;
    int warp = tid >> 5;
    int wm = (warp & 1) * 64;
    int wn = (warp >> 1) * 32;

    const float* Ab = A  + (size_t)blockIdx.y * 128 * K;
    const float* Bb = Bm + (size_t)blockIdx.x * 128 * K;

    int lr = tid >> 3;
    int lc = (tid & 7) * 4;

    float4 pa[4], pb[4];
#pragma unroll
    for (int r = 0; r < 4; r++) {
        pa[r] = *(const float4*)(Ab + (size_t)(lr + r * 32) * K + lc);
        pb[r] = *(const float4*)(Bb + (size_t)(lr + r * 32) * K + lc);
    }

    float acc[16][4];
#pragma unroll
    for (int t = 0; t < 16; t++)
#pragma unroll
        for (int e = 0; e < 4; e++) acc[t][e] = 0.0f;

    int fr = lane >> 2;
    int fc = lane & 3;

    for (int k0 = 0; k0 < K; k0 += 32) {
#pragma unroll
        for (int r = 0; r < 4; r++) {
            uint4 ua, ub;
            ua.x = f2tf32(pa[r].x); ua.y = f2tf32(pa[r].y);
            ua.z = f2tf32(pa[r].z); ua.w = f2tf32(pa[r].w);
            ub.x = f2tf32(pb[r].x); ub.y = f2tf32(pb[r].y);
            ub.z = f2tf32(pb[r].z); ub.w = f2tf32(pb[r].w);
            *(uint4*)&As[(lr + r * 32) * SPITCH + lc] = ua;
            *(uint4*)&Bs[(lr + r * 32) * SPITCH + lc] = ub;
        }
        __syncthreads();

        if (k0 + 32 < K) {
#pragma unroll
            for (int r = 0; r < 4; r++) {
                pa[r] = *(const float4*)(Ab + (size_t)(lr + r * 32) * K + k0 + 32 + lc);
                pb[r] = *(const float4*)(Bb + (size_t)(lr + r * 32) * K + k0 + 32 + lc);
            }
        }

#pragma unroll
        for (int ks = 0; ks < 4; ks++) {
            int kb = ks * 8;
            unsigned af[4][4], bf[4][2];
#pragma unroll
            for (int i = 0; i < 4; i++) {
                int m = wm + i * 16 + fr;
                af[i][0] = As[m * SPITCH + kb + fc];
                af[i][1] = As[(m + 8) * SPITCH + kb + fc];
                af[i][2] = As[m * SPITCH + kb + fc + 4];
                af[i][3] = As[(m + 8) * SPITCH + kb + fc + 4];
            }
#pragma unroll
            for (int j = 0; j < 4; j++) {
                int n = wn + j * 8 + fr;
                bf[j][0] = Bs[n * SPITCH + kb + fc];
                bf[j][1] = Bs[n * SPITCH + kb + fc + 4];
            }
#pragma unroll
            for (int i = 0; i < 4; i++)
#pragma unroll
                for (int j = 0; j < 4; j++)
                    mma_tf32(acc[i * 4 + j], af[i][0], af[i][1], af[i][2], af[i][3],
                             bf[j][0], bf[j][1]);
        }
        __syncthreads();
    }

    int c2 = (lane & 3) * 2;
#pragma unroll
    for (int i = 0; i < 4; i++) {
        size_t row0 = (size_t)blockIdx.y * 128 + wm + i * 16 + fr;
#pragma unroll
        for (int j = 0; j < 4; j++) {
            float* d = acc[i * 4 + j];
            size_t col = (size_t)blockIdx.x * 128 + wn + j * 8 + c2;
            *(float2*)&C[row0 * N + col]       = make_float2(d[0], d[1]);
            *(float2*)&C[(row0 + 8) * N + col] = make_float2(d[2], d[3]);
        }
    }
}

// ---------------------------------------------------------------------------
// RMSNorm + RoPE + scatter into q/k/v buffers (outputs stored as tf32 bits).
// ---------------------------------------------------------------------------
__global__ __launch_bounds__(512) void norm_rope_kernel(
        const float* __restrict__ fcos, const float* __restrict__ fsin,
        const int*   __restrict__ kvidx,
        const float* __restrict__ qw, const float* __restrict__ kw)
{
    int token = blockIdx.x;
    int b = token / NS;
    int s = token - b * NS;
    int warp = threadIdx.x >> 5;
    int lane = threadIdx.x & 31;

    const float* src = g_qkv + (size_t)token * ((NH + 2 * NKV) * ND) + warp * ND;

    float x1[4], x2[4];
#pragma unroll
    for (int i = 0; i < 4; i++) {
        x1[i] = src[lane + 32 * i];
        x2[i] = src[128 + lane + 32 * i];
    }

    if (warp >= 12) { // V: copy (as tf32 bits)
        int kh = warp - 12;
        unsigned* dst = (unsigned*)(g_v + ((size_t)(b * NKV + kh) * NS + kvidx[s]) * ND);
#pragma unroll
        for (int i = 0; i < 4; i++) {
            dst[lane + 32 * i]       = f2tf32(x1[i]);
            dst[128 + lane + 32 * i] = f2tf32(x2[i]);
        }
        return;
    }

    float ss = 0.0f;
#pragma unroll
    for (int i = 0; i < 4; i++) ss += x1[i] * x1[i] + x2[i] * x2[i];
#pragma unroll
    for (int m = 16; m; m >>= 1) ss += __shfl_xor_sync(0xffffffffu, ss, m);
    float inv = rsqrtf(ss * (1.0f / ND) + 1e-6f);

    const float* w   = (warp < 8) ? qw : kw;
    float scale      = (warp < 8) ? 0.0625f : 1.0f; // SCALING folded into q
    unsigned* dst;
    if (warp < 8) dst = (unsigned*)(g_q + ((size_t)(b * NH + warp) * NS + s) * ND);
    else          dst = (unsigned*)(g_k + ((size_t)(b * NKV + (warp - 8)) * NS + kvidx[s]) * ND);

#pragma unroll
    for (int i = 0; i < 4; i++) {
        int d = lane + 32 * i;
        float c  = fcos[(size_t)s * 128 + d];
        float sn = fsin[(size_t)s * 128 + d];
        float y1 = x1[i] * inv * (1.0f + w[d]);
        float y2 = x2[i] * inv * (1.0f + w[d + 128]);
        dst[d]       = f2tf32((y1 * c - y2 * sn) * scale);
        dst[d + 128] = f2tf32((y2 * c + y1 * sn) * scale);
    }
}

// ---------------------------------------------------------------------------
// Sliding-window flash attention, tf32 mma, cp.async double-buffered KV.
// BM=64, BN=32, 256 threads (8 warps).
// QK: warp (wr=warp&3, wc=warp>>2): rows 16wr.., keys 16wc.. (2 n-tiles)
// PV: warp owns d-slice [32*warp, +32) over all 64 rows, k=32.
// ---------------------------------------------------------------------------
#define TP 264
#define PP 36

__global__ __launch_bounds__(256, 1) void attn_mma_kernel()
{
    extern __shared__ float smf[];
    unsigned* Qs  = (unsigned*)smf;            // [64][TP]
    unsigned* Kb0 = Qs  + 64 * TP;             // [2][32][TP]
    unsigned* Vb0 = Kb0 + 2 * 32 * TP;         // [2][32][TP]
    float*    Ps  = (float*)(Vb0 + 2 * 32 * TP); // [64][PP]
    float*    ms  = Ps + 64 * PP;              // [64]
    float*    ls  = ms + 64;
    float*    cs  = ls + 64;

    int qt = blockIdx.x, h = blockIdx.y, b = blockIdx.z;
    int q0 = qt * 64;
    int kh = h >> 1;

    const float* Qg = g_q + ((size_t)(b * NH + h) * NS + q0) * ND;
    const float* Kg = g_k + (size_t)(b * NKV + kh) * NS * ND;
    const float* Vg = g_v + (size_t)(b * NKV + kh) * NS * ND;

    int tid  = threadIdx.x;
    int lane = tid & 31;
    int warp = tid >> 5;
    int wr = warp & 3;
    int wc = warp >> 2;
    int fr = lane >> 2;
    int fc = lane & 3;

    // Q tile: raw copy (already tf32 bits)
    for (int i = tid; i < 64 * 64; i += 256) {
        int r = i >> 6, c = (i & 63) << 2;
        *(uint4*)&Qs[r * TP + c] = *(const uint4*)(Qg + (size_t)r * ND + c);
    }
    if (tid < 64) { ms[tid] = -1e30f; ls[tid] = 0.0f; }

    float oacc[16][4];
#pragma unroll
    for (int t = 0; t < 16; t++)
#pragma unroll
        for (int e = 0; e < 4; e++) oacc[t][e] = 0.0f;

    // KV tiles of 32 keys
    int ktEnd = 2 * qt + 1;
    int ktBeg = 2 * qt - 32; if (ktBeg < 0) ktBeg = 0;
    int r0 = 16 * wr + fr;

    int ldrow = tid >> 3;          // 0..31
    int ldcb  = (tid & 7) * 32;    // col base (8 float4 each)
    unsigned ksm[2], vsm[2];
    ksm[0] = (unsigned)__cvta_generic_to_shared(Kb0);
    ksm[1] = (unsigned)__cvta_generic_to_shared(Kb0 + 32 * TP);
    vsm[0] = (unsigned)__cvta_generic_to_shared(Vb0);
    vsm[1] = (unsigned)__cvta_generic_to_shared(Vb0 + 32 * TP);

    // prologue: issue first tile into buf 0
    {
        const float* kr = Kg + (size_t)(ktBeg * 32 + ldrow) * ND;
        const float* vr = Vg + (size_t)(ktBeg * 32 + ldrow) * ND;
#pragma unroll
        for (int j = 0; j < 8; j++) {
            int c = ldcb + j * 4;
            cp16(ksm[0] + (unsigned)((ldrow * TP + c) * 4), kr + c);
            cp16(vsm[0] + (unsigned)((ldrow * TP + c) * 4), vr + c);
        }
        asm volatile("cp.async.commit_group;");
    }

    for (int kt = ktBeg; kt <= ktEnd; kt++) {
        int buf = (kt - ktBeg) & 1;
        int k0 = kt * 32;

        __syncthreads(); // A: prior-iter compute done; safe to fill buf^1

        if (kt < ktEnd) {
            const float* kr = Kg + (size_t)((kt + 1) * 32 + ldrow) * ND;
            const float* vr = Vg + (size_t)((kt + 1) * 32 + ldrow) * ND;
#pragma unroll
            for (int j = 0; j < 8; j++) {
                int c = ldcb + j * 4;
                cp16(ksm[buf ^ 1] + (unsigned)((ldrow * TP + c) * 4), kr + c);
                cp16(vsm[buf ^ 1] + (unsigned)((ldrow * TP + c) * 4), vr + c);
            }
            asm volatile("cp.async.commit_group;");
            asm volatile("cp.async.wait_group 1;");
        } else {
            asm volatile("cp.async.wait_group 0;");
        }
        __syncthreads(); // B: tile kt visible

        unsigned* Ks = Kb0 + buf * 32 * TP;
        unsigned* Vs = Vb0 + buf * 32 * TP;

        // ---- scores: m16 x n16 per warp, k=256 ----
        float sacc[2][4];
#pragma unroll
        for (int t = 0; t < 2; t++)
#pragma unroll
            for (int e = 0; e < 4; e++) sacc[t][e] = 0.0f;

#pragma unroll 4
        for (int kb = 0; kb < 256; kb += 8) {
            unsigned a0 = Qs[r0 * TP + kb + fc];
            unsigned a1 = Qs[(r0 + 8) * TP + kb + fc];
            unsigned a2 = Qs[r0 * TP + kb + fc + 4];
            unsigned a3 = Qs[(r0 + 8) * TP + kb + fc + 4];
#pragma unroll
            for (int nt = 0; nt < 2; nt++) {
                int n = 16 * wc + 8 * nt + fr;
                unsigned b0 = Ks[n * TP + kb + fc];
                unsigned b1 = Ks[n * TP + kb + fc + 4];
                mma_tf32(sacc[nt], a0, a1, a2, a3, b0, b1);
            }
        }

        // softcap + mask -> Ps (raw scores, float)
#pragma unroll
        for (int nt = 0; nt < 2; nt++) {
#pragma unroll
            for (int e = 0; e < 4; e++) {
                int r  = r0 + (e >> 1) * 8;
                int kj = k0 + 16 * wc + 8 * nt + 2 * fc + (e & 1);
                int qi = q0 + r;
                float ev = __expf(sacc[nt][e] * 0.04f);
                float v = 50.0f - 100.0f / (ev + 1.0f);
                bool ok = (kj <= qi) && (qi - kj < NWIN);
                sacc[nt][e] = ok ? v : -1e30f;
            }
            int col = 16 * wc + 8 * nt + 2 * fc;
            *(float2*)&Ps[r0 * PP + col]       = make_float2(sacc[nt][0], sacc[nt][1]);
            *(float2*)&Ps[(r0 + 8) * PP + col] = make_float2(sacc[nt][2], sacc[nt][3]);
        }
        __syncthreads(); // C

        // ---- softmax: warp w rows 8w..8w+7; 4 lanes/row, 8 cols/lane ----
        {
            int row = (warp << 3) + (lane >> 2);
            int cb  = lane & 3;
            float vbuf[8];
            float mx = -1e30f;
#pragma unroll
            for (int j = 0; j < 8; j++) {
                vbuf[j] = Ps[row * PP + cb + 4 * j];
                mx = fmaxf(mx, vbuf[j]);
            }
            mx = fmaxf(mx, __shfl_xor_sync(0xffffffffu, mx, 1));
            mx = fmaxf(mx, __shfl_xor_sync(0xffffffffu, mx, 2));
            float mold = ms[row];
            float mnew = fmaxf(mold, mx);
            float corr = __expf(mold - mnew);
            float rs = 0.0f;
#pragma unroll
            for (int j = 0; j < 8; j++) {
                float p = __expf(vbuf[j] - mnew);
                rs += p;
                Ps[row * PP + cb + 4 * j] = __uint_as_float(f2tf32(p));
            }
            rs += __shfl_xor_sync(0xffffffffu, rs, 1);
            rs += __shfl_xor_sync(0xffffffffu, rs, 2);
            if (cb == 0) {
                ms[row] = mnew;
                cs[row] = corr;
                ls[row] = ls[row] * corr + rs;
            }
        }
        __syncthreads(); // D

        // ---- rescale O, then O += P @ V: warp m64 x d32, k=32 ----
        {
            float cr0[4], cr1[4];
#pragma unroll
            for (int mt = 0; mt < 4; mt++) {
                cr0[mt] = cs[16 * mt + fr];
                cr1[mt] = cs[16 * mt + fr + 8];
            }
#pragma unroll
            for (int mt = 0; mt < 4; mt++)
#pragma unroll
                for (int nt = 0; nt < 4; nt++) {
                    float* d = oacc[mt * 4 + nt];
                    d[0] *= cr0[mt]; d[1] *= cr0[mt];
                    d[2] *= cr1[mt]; d[3] *= cr1[mt];
                }
#pragma unroll
            for (int kc = 0; kc < 32; kc += 8) {
                unsigned pa[4][4];
#pragma unroll
                for (int mt = 0; mt < 4; mt++) {
                    int r = 16 * mt + fr;
                    pa[mt][0] = __float_as_uint(Ps[r * PP + kc + fc]);
                    pa[mt][1] = __float_as_uint(Ps[(r + 8) * PP + kc + fc]);
                    pa[mt][2] = __float_as_uint(Ps[r * PP + kc + fc + 4]);
                    pa[mt][3] = __float_as_uint(Ps[(r + 8) * PP + kc + fc + 4]);
                }
                unsigned vb[4][2];
#pragma unroll
                for (int nt = 0; nt < 4; nt++) {
                    int dn = 32 * warp + 8 * nt + fr;
                    vb[nt][0] = Vs[(kc + fc) * TP + dn];
                    vb[nt][1] = Vs[(kc + fc + 4) * TP + dn];
                }
#pragma unroll
                for (int mt = 0; mt < 4; mt++)
#pragma unroll
                    for (int nt = 0; nt < 4; nt++)
                        mma_tf32(oacc[mt * 4 + nt], pa[mt][0], pa[mt][1], pa[mt][2], pa[mt][3],
                                 vb[nt][0], vb[nt][1]);
            }
        }
    }

    // epilogue
    {
        float* Og = g_att + ((size_t)b * NS + q0) * (NH * ND) + h * ND;
#pragma unroll
        for (int mt = 0; mt < 4; mt++) {
            int r = 16 * mt + fr;
            float il0 = 1.0f / ls[r];
            float il1 = 1.0f / ls[r + 8];
#pragma unroll
            for (int nt = 0; nt < 4; nt++) {
                float* d = oacc[mt * 4 + nt];
                int col = 32 * warp + 8 * nt + 2 * fc;
                *(float2*)&Og[(size_t)r * (NH * ND) + col] =
                    make_float2(d[0] * il0, d[1] * il0);
                *(float2*)&Og[(size_t)(r + 8) * (NH * ND) + col] =
                    make_float2(d[2] * il1, d[3] * il1);
            }
        }
    }
}

// ---------------------------------------------------------------------------
extern "C" void kernel_launch(void* const* d_in, const int* in_sizes, int n_in,
                              void* d_out, int out_size)
{
    const float* hidden = (const float*)d_in[0];
    const float* fcos   = (const float*)d_in[1];
    const float* fsin   = (const float*)d_in[2];
    const int*   kvidx  = (const int*)  d_in[3];
    const float* w_qkv  = (const float*)d_in[8];
    const float* w_o    = (const float*)d_in[9];
    const float* qnw    = (const float*)d_in[10];
    const float* knw    = (const float*)d_in[11];
    float* out = (float*)d_out;

    void* p;
    cudaGetSymbolAddress(&p, g_qkv); float* qkv_ptr = (float*)p;
    cudaGetSymbolAddress(&p, g_att); float* att_ptr = (float*)p;

    // 1) QKV projection (tf32 tensor cores)
    {
        dim3 grid((NH + 2 * NKV) * ND / 128, NB * NS / 128);
        tf32gemm_nt<<<grid, 256>>>(hidden, w_qkv, qkv_ptr,
                                   NB * NS, (NH + 2 * NKV) * ND, NE);
    }

    // 2) RMSNorm + RoPE + cache scatter (tf32 outputs)
    norm_rope_kernel<<<NB * NS, 512>>>(fcos, fsin, kvidx, qnw, knw);

    // 3) sliding-window flash attention (tf32, cp.async pipelined)
    {
        size_t smem = (size_t)(64 * TP + 4 * 32 * TP + 64 * PP + 192) * 4;
        cudaFuncSetAttribute(attn_mma_kernel,
                             cudaFuncAttributeMaxDynamicSharedMemorySize,
                             (int)smem);
        dim3 grid(NS / 64, NH, NB);
        attn_mma_kernel<<<grid, 256, smem>>>();
    }

    // 4) output projection (tf32 tensor cores)
    {
        dim3 grid(NE / 128, NB * NS / 128);
        tf32gemm_nt<<<grid, 256>>>(att_ptr, w_o, out, NB * NS, NE, NH * ND);
    }
}

// round 7
// speedup vs baseline: 1.0449x; 1.0449x over previous
#include <cuda_runtime.h>
#include <math.h>

#define NB   2
#define NS   4096
#define NE   2560
#define NH   8
#define NKV  4
#define ND   256
#define NWIN 1024

// ---------------- scratch (device globals: allocation-free) ----------------
static __device__ float g_qkv[(size_t)NB * NS * (NH + 2 * NKV) * ND]; // [8192, 4096]
static __device__ float g_q  [(size_t)NB * NH  * NS * ND];  // tf32 bits
static __device__ float g_k  [(size_t)NB * NKV * NS * ND];  // tf32 bits
static __device__ float g_v  [(size_t)NB * NKV * NS * ND];  // tf32 bits
static __device__ float g_att[(size_t)NB * NS * NH * ND];   // fp32

__device__ __forceinline__ unsigned f2tf32(float f) {
    unsigned u;
    asm volatile("cvt.rna.tf32.f32 %0, %1;" : "=r"(u) : "f"(f));
    return u;
}

__device__ __forceinline__ void mma_tf32(float* d,
        unsigned a0, unsigned a1, unsigned a2, unsigned a3,
        unsigned b0, unsigned b1) {
    asm volatile(
        "mma.sync.aligned.m16n8k8.row.col.f32.tf32.tf32.f32 "
        "{%0,%1,%2,%3},{%4,%5,%6,%7},{%8,%9},{%0,%1,%2,%3};"
        : "+f"(d[0]), "+f"(d[1]), "+f"(d[2]), "+f"(d[3])
        : "r"(a0), "r"(a1), "r"(a2), "r"(a3), "r"(b0), "r"(b1));
}

__device__ __forceinline__ void cp16(unsigned smem_addr, const void* gptr) {
    asm volatile("cp.async.cg.shared.global [%0], [%1], 16;"
                 :: "r"(smem_addr), "l"(gptr));
}

// ---------------------------------------------------------------------------
// TF32 tensor-core GEMM: C[M,N] = A[M,K] @ B[N,K]^T  (round-3 proven config)
// 128x128 tile, BK=32, 256 threads (8 warps, 64x32 each).
// ---------------------------------------------------------------------------
#define SPITCH 36

__global__ __launch_bounds__(256, 1) void tf32gemm_nt(
        const float* __restrict__ A, const float* __restrict__ Bm,
        float* __restrict__ C, int M, int N, int K)
{
    __shared__ unsigned As[128 * SPITCH];
    __shared__ unsigned Bs[128 * SPITCH];

    int tid  = threadIdx.x;
    int lane = tid & 31;
    int warp = tid >> 5;
    int wm = (warp & 1) * 64;
    int wn = (warp >> 1) * 32;

    const float* Ab = A  + (size_t)blockIdx.y * 128 * K;
    const float* Bb = Bm + (size_t)blockIdx.x * 128 * K;

    int lr = tid >> 3;
    int lc = (tid & 7) * 4;

    float4 pa[4], pb[4];
#pragma unroll
    for (int r = 0; r < 4; r++) {
        pa[r] = *(const float4*)(Ab + (size_t)(lr + r * 32) * K + lc);
        pb[r] = *(const float4*)(Bb + (size_t)(lr + r * 32) * K + lc);
    }

    float acc[16][4];
#pragma unroll
    for (int t = 0; t < 16; t++)
#pragma unroll
        for (int e = 0; e < 4; e++) acc[t][e] = 0.0f;

    int fr = lane >> 2;
    int fc = lane & 3;

    for (int k0 = 0; k0 < K; k0 += 32) {
#pragma unroll
        for (int r = 0; r < 4; r++) {
            uint4 ua, ub;
            ua.x = f2tf32(pa[r].x); ua.y = f2tf32(pa[r].y);
            ua.z = f2tf32(pa[r].z); ua.w = f2tf32(pa[r].w);
            ub.x = f2tf32(pb[r].x); ub.y = f2tf32(pb[r].y);
            ub.z = f2tf32(pb[r].z); ub.w = f2tf32(pb[r].w);
            *(uint4*)&As[(lr + r * 32) * SPITCH + lc] = ua;
            *(uint4*)&Bs[(lr + r * 32) * SPITCH + lc] = ub;
        }
        __syncthreads();

        if (k0 + 32 < K) {
#pragma unroll
            for (int r = 0; r < 4; r++) {
                pa[r] = *(const float4*)(Ab + (size_t)(lr + r * 32) * K + k0 + 32 + lc);
                pb[r] = *(const float4*)(Bb + (size_t)(lr + r * 32) * K + k0 + 32 + lc);
            }
        }

#pragma unroll
        for (int ks = 0; ks < 4; ks++) {
            int kb = ks * 8;
            unsigned af[4][4], bf[4][2];
#pragma unroll
            for (int i = 0; i < 4; i++) {
                int m = wm + i * 16 + fr;
                af[i][0] = As[m * SPITCH + kb + fc];
                af[i][1] = As[(m + 8) * SPITCH + kb + fc];
                af[i][2] = As[m * SPITCH + kb + fc + 4];
                af[i][3] = As[(m + 8) * SPITCH + kb + fc + 4];
            }
#pragma unroll
            for (int j = 0; j < 4; j++) {
                int n = wn + j * 8 + fr;
                bf[j][0] = Bs[n * SPITCH + kb + fc];
                bf[j][1] = Bs[n * SPITCH + kb + fc + 4];
            }
#pragma unroll
            for (int i = 0; i < 4; i++)
#pragma unroll
                for (int j = 0; j < 4; j++)
                    mma_tf32(acc[i * 4 + j], af[i][0], af[i][1], af[i][2], af[i][3],
                             bf[j][0], bf[j][1]);
        }
        __syncthreads();
    }

    int c2 = (lane & 3) * 2;
#pragma unroll
    for (int i = 0; i < 4; i++) {
        size_t row0 = (size_t)blockIdx.y * 128 + wm + i * 16 + fr;
#pragma unroll
        for (int j = 0; j < 4; j++) {
            float* d = acc[i * 4 + j];
            size_t col = (size_t)blockIdx.x * 128 + wn + j * 8 + c2;
            *(float2*)&C[row0 * N + col]       = make_float2(d[0], d[1]);
            *(float2*)&C[(row0 + 8) * N + col] = make_float2(d[2], d[3]);
        }
    }
}

// ---------------------------------------------------------------------------
// RMSNorm + RoPE + scatter into q/k/v buffers (outputs stored as tf32 bits).
// ---------------------------------------------------------------------------
__global__ __launch_bounds__(512) void norm_rope_kernel(
        const float* __restrict__ fcos, const float* __restrict__ fsin,
        const int*   __restrict__ kvidx,
        const float* __restrict__ qw, const float* __restrict__ kw)
{
    int token = blockIdx.x;
    int b = token / NS;
    int s = token - b * NS;
    int warp = threadIdx.x >> 5;
    int lane = threadIdx.x & 31;

    const float* src = g_qkv + (size_t)token * ((NH + 2 * NKV) * ND) + warp * ND;

    float x1[4], x2[4];
#pragma unroll
    for (int i = 0; i < 4; i++) {
        x1[i] = src[lane + 32 * i];
        x2[i] = src[128 + lane + 32 * i];
    }

    if (warp >= 12) { // V: copy (as tf32 bits)
        int kh = warp - 12;
        unsigned* dst = (unsigned*)(g_v + ((size_t)(b * NKV + kh) * NS + kvidx[s]) * ND);
#pragma unroll
        for (int i = 0; i < 4; i++) {
            dst[lane + 32 * i]       = f2tf32(x1[i]);
            dst[128 + lane + 32 * i] = f2tf32(x2[i]);
        }
        return;
    }

    float ss = 0.0f;
#pragma unroll
    for (int i = 0; i < 4; i++) ss += x1[i] * x1[i] + x2[i] * x2[i];
#pragma unroll
    for (int m = 16; m; m >>= 1) ss += __shfl_xor_sync(0xffffffffu, ss, m);
    float inv = rsqrtf(ss * (1.0f / ND) + 1e-6f);

    const float* w   = (warp < 8) ? qw : kw;
    float scale      = (warp < 8) ? 0.0625f : 1.0f; // SCALING folded into q
    unsigned* dst;
    if (warp < 8) dst = (unsigned*)(g_q + ((size_t)(b * NH + warp) * NS + s) * ND);
    else          dst = (unsigned*)(g_k + ((size_t)(b * NKV + (warp - 8)) * NS + kvidx[s]) * ND);

#pragma unroll
    for (int i = 0; i < 4; i++) {
        int d = lane + 32 * i;
        float c  = fcos[(size_t)s * 128 + d];
        float sn = fsin[(size_t)s * 128 + d];
        float y1 = x1[i] * inv * (1.0f + w[d]);
        float y2 = x2[i] * inv * (1.0f + w[d + 128]);
        dst[d]       = f2tf32((y1 * c - y2 * sn) * scale);
        dst[d + 128] = f2tf32((y2 * c + y1 * sn) * scale);
    }
}

// ---------------------------------------------------------------------------
// Sliding-window flash attention, tf32 mma, BM=BN=64, 256 threads (8 warps).
// Single-buffered K/V with phase-disjoint cp.async pipelining:
//   V(kt)   issued at loop top      -> overlaps QK(kt)+softmax(kt)
//   K(kt+1) issued after sync C     -> overlaps softmax(kt)+PV(kt)
// QK: warp (wr=warp&3, wc=warp>>2): rows 16wr.., keys 32wc.. (4 n-tiles)
// PV: warp owns d-slice [32*warp, +32) over all 64 rows, k=64.
// ---------------------------------------------------------------------------
#define TP 264
#define PP 68

__global__ __launch_bounds__(256, 1) void attn_mma_kernel()
{
    extern __shared__ float smf[];
    unsigned* Qs = (unsigned*)smf;           // [64][TP]
    unsigned* Ks = Qs + 64 * TP;             // [64][TP]
    unsigned* Vs = Ks + 64 * TP;             // [64][TP]
    float*    Ps = (float*)(Vs + 64 * TP);   // [64][PP]
    float*    ms = Ps + 64 * PP;             // [64]
    float*    ls = ms + 64;
    float*    cs = ls + 64;

    int qt = blockIdx.x, h = blockIdx.y, b = blockIdx.z;
    int q0 = qt * 64;
    int kh = h >> 1;

    const float* Qg = g_q + ((size_t)(b * NH + h) * NS + q0) * ND;
    const float* Kg = g_k + (size_t)(b * NKV + kh) * NS * ND;
    const float* Vg = g_v + (size_t)(b * NKV + kh) * NS * ND;

    int tid  = threadIdx.x;
    int lane = tid & 31;
    int warp = tid >> 5;
    int wr = warp & 3;
    int wc = warp >> 2;
    int fr = lane >> 2;
    int fc = lane & 3;

    // loader mapping: 64 rows, 4 threads per row, 16 float4 each
    int ldrow = tid >> 2;          // 0..63
    int ldcb  = (tid & 3) * 64;    // col base
    unsigned ksm = (unsigned)__cvta_generic_to_shared(Ks);
    unsigned vsm = (unsigned)__cvta_generic_to_shared(Vs);

    // Q tile: raw copy (already tf32 bits)
    for (int i = tid; i < 64 * 64; i += 256) {
        int r = i >> 6, c = (i & 63) << 2;
        *(uint4*)&Qs[r * TP + c] = *(const uint4*)(Qg + (size_t)r * ND + c);
    }
    if (tid < 64) { ms[tid] = -1e30f; ls[tid] = 0.0f; }

    float oacc[16][4];
#pragma unroll
    for (int t = 0; t < 16; t++)
#pragma unroll
        for (int e = 0; e < 4; e++) oacc[t][e] = 0.0f;

    int t0 = qt - 16; if (t0 < 0) t0 = 0;
    int r0 = 16 * wr + fr;

    // prologue: issue K(t0)
    {
        const float* kr = Kg + (size_t)(t0 * 64 + ldrow) * ND + ldcb;
        unsigned dst = ksm + (unsigned)((ldrow * TP + ldcb) * 4);
#pragma unroll
        for (int j = 0; j < 16; j++) cp16(dst + j * 16, kr + j * 4);
        asm volatile("cp.async.commit_group;");
    }

    for (int kt = t0; kt <= qt; kt++) {
        int k0 = kt * 64;

        __syncthreads(); // A: PV(kt-1) done -> V buffer free (iter0: Q stores placed)

        // issue V(kt): overlaps QK+softmax below
        {
            const float* vr = Vg + (size_t)(k0 + ldrow) * ND + ldcb;
            unsigned dst = vsm + (unsigned)((ldrow * TP + ldcb) * 4);
#pragma unroll
            for (int j = 0; j < 16; j++) cp16(dst + j * 16, vr + j * 4);
            asm volatile("cp.async.commit_group;");
        }
        asm volatile("cp.async.wait_group 1;"); // K(kt) complete
        __syncthreads(); // B: K(kt) + Q visible to all

        // ---- scores: m16 x n32 per warp, k=256 ----
        float sacc[4][4];
#pragma unroll
        for (int t = 0; t < 4; t++)
#pragma unroll
            for (int e = 0; e < 4; e++) sacc[t][e] = 0.0f;

#pragma unroll 4
        for (int kb = 0; kb < 256; kb += 8) {
            unsigned a0 = Qs[r0 * TP + kb + fc];
            unsigned a1 = Qs[(r0 + 8) * TP + kb + fc];
            unsigned a2 = Qs[r0 * TP + kb + fc + 4];
            unsigned a3 = Qs[(r0 + 8) * TP + kb + fc + 4];
#pragma unroll
            for (int nt = 0; nt < 4; nt++) {
                int n = 32 * wc + 8 * nt + fr;
                unsigned b0 = Ks[n * TP + kb + fc];
                unsigned b1 = Ks[n * TP + kb + fc + 4];
                mma_tf32(sacc[nt], a0, a1, a2, a3, b0, b1);
            }
        }

        // softcap + mask -> Ps (raw scores, float)
        // 50*tanh(s/50) = 50 - 100/(exp(s/25)+1)
#pragma unroll
        for (int nt = 0; nt < 4; nt++) {
#pragma unroll
            for (int e = 0; e < 4; e++) {
                int r  = r0 + (e >> 1) * 8;
                int kj = k0 + 32 * wc + 8 * nt + 2 * fc + (e & 1);
                int qi = q0 + r;
                float ev = __expf(sacc[nt][e] * 0.04f);
                float v = 50.0f - 100.0f / (ev + 1.0f);
                bool ok = (kj <= qi) && (qi - kj < NWIN);
                sacc[nt][e] = ok ? v : -1e30f;
            }
            int col = 32 * wc + 8 * nt + 2 * fc;
            *(float2*)&Ps[r0 * PP + col]       = make_float2(sacc[nt][0], sacc[nt][1]);
            *(float2*)&Ps[(r0 + 8) * PP + col] = make_float2(sacc[nt][2], sacc[nt][3]);
        }
        __syncthreads(); // C: Ps ready; K buffer fully consumed

        // issue K(kt+1): overlaps softmax + PV below
        if (kt < qt) {
            const float* kr = Kg + (size_t)((kt + 1) * 64 + ldrow) * ND + ldcb;
            unsigned dst = ksm + (unsigned)((ldrow * TP + ldcb) * 4);
#pragma unroll
            for (int j = 0; j < 16; j++) cp16(dst + j * 16, kr + j * 4);
            asm volatile("cp.async.commit_group;");
        }

        // ---- softmax: warp w owns rows 8w..8w+7; 4 lanes per row ----
        {
            int row = (warp << 3) + (lane >> 2);
            int cb  = lane & 3;
            float vbuf[16];
            float mx = -1e30f;
#pragma unroll
            for (int j = 0; j < 16; j++) {
                vbuf[j] = Ps[row * PP + cb + 4 * j];
                mx = fmaxf(mx, vbuf[j]);
            }
            mx = fmaxf(mx, __shfl_xor_sync(0xffffffffu, mx, 1));
            mx = fmaxf(mx, __shfl_xor_sync(0xffffffffu, mx, 2));
            float mold = ms[row];
            float mnew = fmaxf(mold, mx);
            float corr = __expf(mold - mnew);
            float rs = 0.0f;
#pragma unroll
            for (int j = 0; j < 16; j++) {
                float p = __expf(vbuf[j] - mnew);
                rs += p;
                Ps[row * PP + cb + 4 * j] = __uint_as_float(f2tf32(p));
            }
            rs += __shfl_xor_sync(0xffffffffu, rs, 1);
            rs += __shfl_xor_sync(0xffffffffu, rs, 2);
            if (cb == 0) {
                ms[row] = mnew;
                cs[row] = corr;
                ls[row] = ls[row] * corr + rs;
            }
        }

        // V(kt) must be complete before PV (K(kt+1) may still be in flight)
        if (kt < qt) asm volatile("cp.async.wait_group 1;");
        else         asm volatile("cp.async.wait_group 0;");
        __syncthreads(); // D: P (tf32) + V visible

        // ---- rescale O, then O += P @ V: warp m64 x d32, k=64 ----
        {
            float cr0[4], cr1[4];
#pragma unroll
            for (int mt = 0; mt < 4; mt++) {
                cr0[mt] = cs[16 * mt + fr];
                cr1[mt] = cs[16 * mt + fr + 8];
            }
#pragma unroll
            for (int mt = 0; mt < 4; mt++)
#pragma unroll
                for (int nt = 0; nt < 4; nt++) {
                    float* d = oacc[mt * 4 + nt];
                    d[0] *= cr0[mt]; d[1] *= cr0[mt];
                    d[2] *= cr1[mt]; d[3] *= cr1[mt];
                }
#pragma unroll
            for (int kc = 0; kc < 64; kc += 8) {
                unsigned pa[4][4];
#pragma unroll
                for (int mt = 0; mt < 4; mt++) {
                    int r = 16 * mt + fr;
                    pa[mt][0] = __float_as_uint(Ps[r * PP + kc + fc]);
                    pa[mt][1] = __float_as_uint(Ps[(r + 8) * PP + kc + fc]);
                    pa[mt][2] = __float_as_uint(Ps[r * PP + kc + fc + 4]);
                    pa[mt][3] = __float_as_uint(Ps[(r + 8) * PP + kc + fc + 4]);
                }
                unsigned vb[4][2];
#pragma unroll
                for (int nt = 0; nt < 4; nt++) {
                    int dn = 32 * warp + 8 * nt + fr;
                    vb[nt][0] = Vs[(kc + fc) * TP + dn];
                    vb[nt][1] = Vs[(kc + fc + 4) * TP + dn];
                }
#pragma unroll
                for (int mt = 0; mt < 4; mt++)
#pragma unroll
                    for (int nt = 0; nt < 4; nt++)
                        mma_tf32(oacc[mt * 4 + nt], pa[mt][0], pa[mt][1], pa[mt][2], pa[mt][3],
                                 vb[nt][0], vb[nt][1]);
            }
        }
    }

    // epilogue
    {
        float* Og = g_att + ((size_t)b * NS + q0) * (NH * ND) + h * ND;
#pragma unroll
        for (int mt = 0; mt < 4; mt++) {
            int r = 16 * mt + fr;
            float il0 = 1.0f / ls[r];
            float il1 = 1.0f / ls[r + 8];
#pragma unroll
            for (int nt = 0; nt < 4; nt++) {
                float* d = oacc[mt * 4 + nt];
                int col = 32 * warp + 8 * nt + 2 * fc;
                *(float2*)&Og[(size_t)r * (NH * ND) + col] =
                    make_float2(d[0] * il0, d[1] * il0);
                *(float2*)&Og[(size_t)(r + 8) * (NH * ND) + col] =
                    make_float2(d[2] * il1, d[3] * il1);
            }
        }
    }
}

// ---------------------------------------------------------------------------
extern "C" void kernel_launch(void* const* d_in, const int* in_sizes, int n_in,
                              void* d_out, int out_size)
{
    const float* hidden = (const float*)d_in[0];
    const float* fcos   = (const float*)d_in[1];
    const float* fsin   = (const float*)d_in[2];
    const int*   kvidx  = (const int*)  d_in[3];
    const float* w_qkv  = (const float*)d_in[8];
    const float* w_o    = (const float*)d_in[9];
    const float* qnw    = (const float*)d_in[10];
    const float* knw    = (const float*)d_in[11];
    float* out = (float*)d_out;

    void* p;
    cudaGetSymbolAddress(&p, g_qkv); float* qkv_ptr = (float*)p;
    cudaGetSymbolAddress(&p, g_att); float* att_ptr = (float*)p;

    // 1) QKV projection (tf32 tensor cores)
    {
        dim3 grid((NH + 2 * NKV) * ND / 128, NB * NS / 128);
        tf32gemm_nt<<<grid, 256>>>(hidden, w_qkv, qkv_ptr,
                                   NB * NS, (NH + 2 * NKV) * ND, NE);
    }

    // 2) RMSNorm + RoPE + cache scatter (tf32 outputs)
    norm_rope_kernel<<<NB * NS, 512>>>(fcos, fsin, kvidx, qnw, knw);

    // 3) sliding-window flash attention (tf32, phase-disjoint cp.async)
    {
        size_t smem = (size_t)(3 * 64 * TP + 64 * PP + 192) * 4;
        cudaFuncSetAttribute(attn_mma_kernel,
                             cudaFuncAttributeMaxDynamicSharedMemorySize,
                             (int)smem);
        dim3 grid(NS / 64, NH, NB);
        attn_mma_kernel<<<grid, 256, smem>>>();
    }

    // 4) output projection (tf32 tensor cores)
    {
        dim3 grid(NE / 128, NB * NS / 128);
        tf32gemm_nt<<<grid, 256>>>(att_ptr, w_o, out, NB * NS, NE, NH * ND);
    }
}

// round 8
// speedup vs baseline: 1.1212x; 1.0731x over previous
#include <cuda_runtime.h>
#include <cuda_fp16.h>
#include <math.h>

#define NB   2
#define NS   4096
#define NE   2560
#define NH   8
#define NKV  4
#define ND   256
#define NWIN 1024

// ---------------- scratch (device globals: allocation-free) ----------------
static __device__ float  g_qkv[(size_t)NB * NS * (NH + 2 * NKV) * ND]; // f32
static __device__ __half g_q  [(size_t)NB * NH  * NS * ND];            // fp16
static __device__ __half g_k  [(size_t)NB * NKV * NS * ND];
static __device__ __half g_v  [(size_t)NB * NKV * NS * ND];
static __device__ __half g_att[(size_t)NB * NS * NH * ND];             // fp16

__device__ __forceinline__ unsigned h2u(float x, float y) {
    __half2 h = __floats2half2_rn(x, y);
    return *reinterpret_cast<unsigned*>(&h);
}

__device__ __forceinline__ void mma_f16(float* d,
        unsigned a0, unsigned a1, unsigned a2, unsigned a3,
        unsigned b0, unsigned b1) {
    asm volatile(
        "mma.sync.aligned.m16n8k16.row.col.f32.f16.f16.f32 "
        "{%0,%1,%2,%3},{%4,%5,%6,%7},{%8,%9},{%0,%1,%2,%3};"
        : "+f"(d[0]), "+f"(d[1]), "+f"(d[2]), "+f"(d[3])
        : "r"(a0), "r"(a1), "r"(a2), "r"(a3), "r"(b0), "r"(b1));
}

// ---------------------------------------------------------------------------
// FP16 tensor-core GEMM: C[M,N] = A[M,K] @ B[N,K]^T  (row-major, K contig)
// 128x128 tile, BK=64, 256 threads (8 warps, 64x32 each), m16n8k16.
// A may be float (converted on store) or __half (raw copy). B is float.
// ---------------------------------------------------------------------------
#define GP 36  // smem pitch in uints (half2 units); 36 % 32 == 4 -> conflict-free

template<typename TA>
__global__ __launch_bounds__(256, 1) void h16gemm_nt(
        const TA* __restrict__ A, const float* __restrict__ Bm,
        float* __restrict__ C, int M, int N, int K)
{
    constexpr bool AHALF = (sizeof(TA) == 2);
    __shared__ unsigned As[128 * GP];
    __shared__ unsigned Bs[128 * GP];

    int tid  = threadIdx.x;
    int lane = tid & 31;
    int warp = tid >> 5;
    int wm = (warp & 1) * 64;
    int wn = (warp >> 1) * 32;

    const TA*    Ab = A  + (size_t)blockIdx.y * 128 * K;
    const float* Bb = Bm + (size_t)blockIdx.x * 128 * K;

    int lr  = tid >> 1;          // row 0..127
    int lcf = (tid & 1) * 32;    // element col base (32 elems per thread)
    int ub  = lr * GP + (tid & 1) * 16; // smem uint base

    // prefetch registers
    float4 pa[8]; uint4 ha[4]; float4 pb[8];
    if (AHALF) {
        const uint4* ar = (const uint4*)((const __half*)Ab + (size_t)lr * K + lcf);
#pragma unroll
        for (int j = 0; j < 4; j++) ha[j] = ar[j];
    } else {
        const float* ar = (const float*)Ab + (size_t)lr * K + lcf;
#pragma unroll
        for (int j = 0; j < 8; j++) pa[j] = *(const float4*)(ar + 4 * j);
    }
    {
        const float* br = Bb + (size_t)lr * K + lcf;
#pragma unroll
        for (int j = 0; j < 8; j++) pb[j] = *(const float4*)(br + 4 * j);
    }

    float acc[16][4];
#pragma unroll
    for (int t = 0; t < 16; t++)
#pragma unroll
        for (int e = 0; e < 4; e++) acc[t][e] = 0.0f;

    int fr = lane >> 2;
    int fc = lane & 3;

    for (int k0 = 0; k0 < K; k0 += 64) {
        // commit prefetched chunk
        if (AHALF) {
#pragma unroll
            for (int j = 0; j < 4; j++) *(uint4*)&As[ub + 4 * j] = ha[j];
        } else {
#pragma unroll
            for (int j = 0; j < 4; j++) {
                uint4 u;
                u.x = h2u(pa[2*j].x,   pa[2*j].y);
                u.y = h2u(pa[2*j].z,   pa[2*j].w);
                u.z = h2u(pa[2*j+1].x, pa[2*j+1].y);
                u.w = h2u(pa[2*j+1].z, pa[2*j+1].w);
                *(uint4*)&As[ub + 4 * j] = u;
            }
        }
#pragma unroll
        for (int j = 0; j < 4; j++) {
            uint4 u;
            u.x = h2u(pb[2*j].x,   pb[2*j].y);
            u.y = h2u(pb[2*j].z,   pb[2*j].w);
            u.z = h2u(pb[2*j+1].x, pb[2*j+1].y);
            u.w = h2u(pb[2*j+1].z, pb[2*j+1].w);
            *(uint4*)&Bs[ub + 4 * j] = u;
        }
        __syncthreads();

        if (k0 + 64 < K) {
            if (AHALF) {
                const uint4* ar = (const uint4*)((const __half*)Ab + (size_t)lr * K + k0 + 64 + lcf);
#pragma unroll
                for (int j = 0; j < 4; j++) ha[j] = ar[j];
            } else {
                const float* ar = (const float*)Ab + (size_t)lr * K + k0 + 64 + lcf;
#pragma unroll
                for (int j = 0; j < 8; j++) pa[j] = *(const float4*)(ar + 4 * j);
            }
            const float* br = Bb + (size_t)lr * K + k0 + 64 + lcf;
#pragma unroll
            for (int j = 0; j < 8; j++) pb[j] = *(const float4*)(br + 4 * j);
        }

#pragma unroll
        for (int ks = 0; ks < 4; ks++) {
            int ku = ks * 8;
            unsigned af[4][4], bf[4][2];
#pragma unroll
            for (int i = 0; i < 4; i++) {
                int m = wm + i * 16 + fr;
                af[i][0] = As[m * GP + ku + fc];
                af[i][1] = As[(m + 8) * GP + ku + fc];
                af[i][2] = As[m * GP + ku + fc + 4];
                af[i][3] = As[(m + 8) * GP + ku + fc + 4];
            }
#pragma unroll
            for (int j = 0; j < 4; j++) {
                int n = wn + j * 8 + fr;
                bf[j][0] = Bs[n * GP + ku + fc];
                bf[j][1] = Bs[n * GP + ku + fc + 4];
            }
#pragma unroll
            for (int i = 0; i < 4; i++)
#pragma unroll
                for (int j = 0; j < 4; j++)
                    mma_f16(acc[i * 4 + j], af[i][0], af[i][1], af[i][2], af[i][3],
                            bf[j][0], bf[j][1]);
        }
        __syncthreads();
    }

    int c2 = (lane & 3) * 2;
#pragma unroll
    for (int i = 0; i < 4; i++) {
        size_t row0 = (size_t)blockIdx.y * 128 + wm + i * 16 + fr;
#pragma unroll
        for (int j = 0; j < 4; j++) {
            float* d = acc[i * 4 + j];
            size_t col = (size_t)blockIdx.x * 128 + wn + j * 8 + c2;
            *(float2*)&C[row0 * N + col]       = make_float2(d[0], d[1]);
            *(float2*)&C[(row0 + 8) * N + col] = make_float2(d[2], d[3]);
        }
    }
}

// ---------------------------------------------------------------------------
// RMSNorm + RoPE + scatter into fp16 q/k/v buffers.
// ---------------------------------------------------------------------------
__global__ __launch_bounds__(512) void norm_rope_kernel(
        const float* __restrict__ fcos, const float* __restrict__ fsin,
        const int*   __restrict__ kvidx,
        const float* __restrict__ qw, const float* __restrict__ kw)
{
    int token = blockIdx.x;
    int b = token / NS;
    int s = token - b * NS;
    int warp = threadIdx.x >> 5;
    int lane = threadIdx.x & 31;

    const float* src = g_qkv + (size_t)token * ((NH + 2 * NKV) * ND) + warp * ND;

    float x1[4], x2[4];
#pragma unroll
    for (int i = 0; i < 4; i++) {
        x1[i] = src[lane + 32 * i];
        x2[i] = src[128 + lane + 32 * i];
    }

    if (warp >= 12) { // V: copy
        int kh = warp - 12;
        __half* dst = g_v + ((size_t)(b * NKV + kh) * NS + kvidx[s]) * ND;
#pragma unroll
        for (int i = 0; i < 4; i++) {
            dst[lane + 32 * i]       = __float2half(x1[i]);
            dst[128 + lane + 32 * i] = __float2half(x2[i]);
        }
        return;
    }

    float ss = 0.0f;
#pragma unroll
    for (int i = 0; i < 4; i++) ss += x1[i] * x1[i] + x2[i] * x2[i];
#pragma unroll
    for (int m = 16; m; m >>= 1) ss += __shfl_xor_sync(0xffffffffu, ss, m);
    float inv = rsqrtf(ss * (1.0f / ND) + 1e-6f);

    const float* w   = (warp < 8) ? qw : kw;
    float scale      = (warp < 8) ? 0.0625f : 1.0f; // SCALING folded into q
    __half* dst;
    if (warp < 8) dst = g_q + ((size_t)(b * NH + warp) * NS + s) * ND;
    else          dst = g_k + ((size_t)(b * NKV + (warp - 8)) * NS + kvidx[s]) * ND;

#pragma unroll
    for (int i = 0; i < 4; i++) {
        int d = lane + 32 * i;
        float c  = fcos[(size_t)s * 128 + d];
        float sn = fsin[(size_t)s * 128 + d];
        float y1 = x1[i] * inv * (1.0f + w[d]);
        float y2 = x2[i] * inv * (1.0f + w[d + 128]);
        dst[d]       = __float2half((y1 * c - y2 * sn) * scale);
        dst[d + 128] = __float2half((y2 * c + y1 * sn) * scale);
    }
}

// ---------------------------------------------------------------------------
// Sliding-window flash attention, fp16 m16n8k16. BM=BN=64, 256 thr (8 warps).
// QK: warp (wr,wc): rows 16wr.., keys 32wc.. (4 n-tiles), k=256.
// Softmax fully in registers; only pmax/psum scalars + fp16 probs hit smem.
// PV: warp owns d-slice [32*warp,+32) over all 64 rows, k=64 (V transposed).
// ---------------------------------------------------------------------------
#define QP2 132   // Q/K pitch in uints (256 halves = 128 uints + pad)
#define VTP 36    // Vt/Pp pitch in uints (64 halves = 32 uints + pad)

__global__ __launch_bounds__(256, 1) void attn_mma_kernel()
{
    extern __shared__ unsigned smu[];
    unsigned* Qs = smu;                    // [64][QP2]
    unsigned* Ks = Qs + 64 * QP2;          // [64][QP2]
    unsigned* Vt = Ks + 64 * QP2;          // [256][VTP]  (d-major, key half2)
    unsigned* Pp = Vt + 256 * VTP;         // [64][VTP]   fp16 probs
    float* pmax = (float*)(Pp + 64 * VTP); // [64][2]
    float* psum = pmax + 128;              // [64][2]
    float* ms   = psum + 128;              // [64]
    float* ls   = ms + 64;                 // [64]
    float* cs   = ls + 64;                 // [64]

    int qt = blockIdx.x, h = blockIdx.y, b = blockIdx.z;
    int q0 = qt * 64;
    int kh = h >> 1;

    const unsigned* Qg = (const unsigned*)(g_q + ((size_t)(b * NH + h) * NS + q0) * ND);
    const unsigned* Kg = (const unsigned*)(g_k + (size_t)(b * NKV + kh) * NS * ND);
    const unsigned* Vg = (const unsigned*)(g_v + (size_t)(b * NKV + kh) * NS * ND);

    int tid  = threadIdx.x;
    int lane = tid & 31;
    int warp = tid >> 5;
    int wr = warp & 3;
    int wc = warp >> 2;
    int fr = lane >> 2;
    int fc = lane & 3;

    // Q tile: raw copy (row = 128 uints)
    for (int i = tid; i < 64 * 32; i += 256) {
        int r = i >> 5, c4 = (i & 31) * 4;
        *(uint4*)&Qs[r * QP2 + c4] = *(const uint4*)(Qg + (size_t)r * 128 + c4);
    }
    if (tid < 64) { ms[tid] = -1e30f; ls[tid] = 0.0f; }

    float oacc[16][4];
#pragma unroll
    for (int t = 0; t < 16; t++)
#pragma unroll
        for (int e = 0; e < 4; e++) oacc[t][e] = 0.0f;

    int t0 = qt - 16; if (t0 < 0) t0 = 0;
    int r0 = 16 * wr + fr;

    for (int kt = t0; kt <= qt; kt++) {
        int k0 = kt * 64;
        __syncthreads(); // A: prev PV done, buffers free

        // K tile copy
        for (int i = tid; i < 64 * 32; i += 256) {
            int r = i >> 5, c4 = (i & 31) * 4;
            *(uint4*)&Ks[r * QP2 + c4] = *(const uint4*)(Kg + (size_t)(k0 + r) * 128 + c4);
        }
        // V tile transposed: tasks = 32 keypairs x 32 d-chunks
#pragma unroll
        for (int t = 0; t < 4; t++) {
            int task = tid + 256 * t;
            int kp = task & 31;        // key pair index
            int dch = task >> 5;       // d chunk (8 halves)
            uint4 va = *(const uint4*)(Vg + (size_t)(k0 + 2 * kp)     * 128 + dch * 4);
            uint4 vb = *(const uint4*)(Vg + (size_t)(k0 + 2 * kp + 1) * 128 + dch * 4);
            int d0 = dch * 8;
            unsigned au[4] = {va.x, va.y, va.z, va.w};
            unsigned bu[4] = {vb.x, vb.y, vb.z, vb.w};
#pragma unroll
            for (int j = 0; j < 4; j++) {
                Vt[(d0 + 2 * j)     * VTP + kp] = __byte_perm(au[j], bu[j], 0x5410);
                Vt[(d0 + 2 * j + 1) * VTP + kp] = __byte_perm(au[j], bu[j], 0x7632);
            }
        }
        __syncthreads(); // B: K, Vt ready

        // ---- scores: m16 x n32 per warp, k=256 (16 k16 steps) ----
        float sacc[4][4];
#pragma unroll
        for (int t = 0; t < 4; t++)
#pragma unroll
            for (int e = 0; e < 4; e++) sacc[t][e] = 0.0f;

#pragma unroll 4
        for (int ku = 0; ku < 128; ku += 8) {
            unsigned a0 = Qs[r0 * QP2 + ku + fc];
            unsigned a1 = Qs[(r0 + 8) * QP2 + ku + fc];
            unsigned a2 = Qs[r0 * QP2 + ku + fc + 4];
            unsigned a3 = Qs[(r0 + 8) * QP2 + ku + fc + 4];
#pragma unroll
            for (int nt = 0; nt < 4; nt++) {
                int n = 32 * wc + 8 * nt + fr;
                unsigned b0 = Ks[n * QP2 + ku + fc];
                unsigned b1 = Ks[n * QP2 + ku + fc + 4];
                mma_f16(sacc[nt], a0, a1, a2, a3, b0, b1);
            }
        }

        // softcap + mask in registers; per-row partial max
        float mx0 = -1e30f, mx1 = -1e30f;
#pragma unroll
        for (int nt = 0; nt < 4; nt++) {
#pragma unroll
            for (int e = 0; e < 4; e++) {
                int r  = r0 + (e >> 1) * 8;
                int kj = k0 + 32 * wc + 8 * nt + 2 * fc + (e & 1);
                int qi = q0 + r;
                float ev = __expf(sacc[nt][e] * 0.04f);
                float v = 50.0f - 100.0f / (ev + 1.0f);
                bool ok = (kj <= qi) && (qi - kj < NWIN);
                v = ok ? v : -1e30f;
                sacc[nt][e] = v;
                if ((e >> 1) == 0) mx0 = fmaxf(mx0, v); else mx1 = fmaxf(mx1, v);
            }
        }
        mx0 = fmaxf(mx0, __shfl_xor_sync(0xffffffffu, mx0, 1));
        mx0 = fmaxf(mx0, __shfl_xor_sync(0xffffffffu, mx0, 2));
        mx1 = fmaxf(mx1, __shfl_xor_sync(0xffffffffu, mx1, 1));
        mx1 = fmaxf(mx1, __shfl_xor_sync(0xffffffffu, mx1, 2));
        if (fc == 0) {
            pmax[r0 * 2 + wc]       = mx0;
            pmax[(r0 + 8) * 2 + wc] = mx1;
        }
        __syncthreads(); // C: pmax complete

        // ---- P phase: probs + partial sums + m/cs update ----
        {
            float mo0 = ms[r0];
            float mo1 = ms[r0 + 8];
            float mn0 = fmaxf(mo0, fmaxf(pmax[r0 * 2], pmax[r0 * 2 + 1]));
            float mn1 = fmaxf(mo1, fmaxf(pmax[(r0 + 8) * 2], pmax[(r0 + 8) * 2 + 1]));
            if (wc == 0 && fc == 0) {
                cs[r0]     = __expf(mo0 - mn0);
                cs[r0 + 8] = __expf(mo1 - mn1);
                ms[r0]     = mn0;   // benign race: later readers get same max
                ms[r0 + 8] = mn1;
            }
            float rs0 = 0.0f, rs1 = 0.0f;
#pragma unroll
            for (int nt = 0; nt < 4; nt++) {
                float p0 = __expf(sacc[nt][0] - mn0);
                float p1 = __expf(sacc[nt][1] - mn0);
                float p2 = __expf(sacc[nt][2] - mn1);
                float p3 = __expf(sacc[nt][3] - mn1);
                rs0 += p0 + p1; rs1 += p2 + p3;
                int cu = 16 * wc + 4 * nt + fc;
                Pp[r0 * VTP + cu]       = h2u(p0, p1);
                Pp[(r0 + 8) * VTP + cu] = h2u(p2, p3);
            }
            rs0 += __shfl_xor_sync(0xffffffffu, rs0, 1);
            rs0 += __shfl_xor_sync(0xffffffffu, rs0, 2);
            rs1 += __shfl_xor_sync(0xffffffffu, rs1, 1);
            rs1 += __shfl_xor_sync(0xffffffffu, rs1, 2);
            if (fc == 0) {
                psum[r0 * 2 + wc]       = rs0;
                psum[(r0 + 8) * 2 + wc] = rs1;
            }
        }
        __syncthreads(); // D: probs + psum + cs visible

        // ---- PV phase: l update, O rescale, O += P @ V ----
        if (tid < 64)
            ls[tid] = ls[tid] * cs[tid] + psum[tid * 2] + psum[tid * 2 + 1];
        {
            float cr0[4], cr1[4];
#pragma unroll
            for (int mt = 0; mt < 4; mt++) {
                cr0[mt] = cs[16 * mt + fr];
                cr1[mt] = cs[16 * mt + fr + 8];
            }
#pragma unroll
            for (int mt = 0; mt < 4; mt++)
#pragma unroll
                for (int nt = 0; nt < 4; nt++) {
                    float* d = oacc[mt * 4 + nt];
                    d[0] *= cr0[mt]; d[1] *= cr0[mt];
                    d[2] *= cr1[mt]; d[3] *= cr1[mt];
                }
#pragma unroll
            for (int ku = 0; ku < 32; ku += 8) {
                unsigned pa[4][4];
#pragma unroll
                for (int mt = 0; mt < 4; mt++) {
                    int r = 16 * mt + fr;
                    pa[mt][0] = Pp[r * VTP + ku + fc];
                    pa[mt][1] = Pp[(r + 8) * VTP + ku + fc];
                    pa[mt][2] = Pp[r * VTP + ku + fc + 4];
                    pa[mt][3] = Pp[(r + 8) * VTP + ku + fc + 4];
                }
                unsigned vb[4][2];
#pragma unroll
                for (int nt = 0; nt < 4; nt++) {
                    int dn = 32 * warp + 8 * nt + fr;
                    vb[nt][0] = Vt[dn * VTP + ku + fc];
                    vb[nt][1] = Vt[dn * VTP + ku + fc + 4];
                }
#pragma unroll
                for (int mt = 0; mt < 4; mt++)
#pragma unroll
                    for (int nt = 0; nt < 4; nt++)
                        mma_f16(oacc[mt * 4 + nt], pa[mt][0], pa[mt][1], pa[mt][2], pa[mt][3],
                                vb[nt][0], vb[nt][1]);
            }
        }
    }
    __syncthreads(); // final ls values visible

    // epilogue: write fp16 att output [b, s, h*D + d]
    {
        unsigned* Og = (unsigned*)(g_att + ((size_t)b * NS + q0) * (NH * ND) + h * ND);
#pragma unroll
        for (int mt = 0; mt < 4; mt++) {
            int r = 16 * mt + fr;
            float il0 = 1.0f / ls[r];
            float il1 = 1.0f / ls[r + 8];
#pragma unroll
            for (int nt = 0; nt < 4; nt++) {
                float* d = oacc[mt * 4 + nt];
                int cu = 16 * warp + 4 * nt + fc; // uint col within head slice
                Og[(size_t)r * 1024 + cu]       = h2u(d[0] * il0, d[1] * il0);
                Og[(size_t)(r + 8) * 1024 + cu] = h2u(d[2] * il1, d[3] * il1);
            }
        }
    }
}

// ---------------------------------------------------------------------------
extern "C" void kernel_launch(void* const* d_in, const int* in_sizes, int n_in,
                              void* d_out, int out_size)
{
    const float* hidden = (const float*)d_in[0];
    const float* fcos   = (const float*)d_in[1];
    const float* fsin   = (const float*)d_in[2];
    const int*   kvidx  = (const int*)  d_in[3];
    const float* w_qkv  = (const float*)d_in[8];
    const float* w_o    = (const float*)d_in[9];
    const float* qnw    = (const float*)d_in[10];
    const float* knw    = (const float*)d_in[11];
    float* out = (float*)d_out;

    void* p;
    cudaGetSymbolAddress(&p, g_qkv); float*  qkv_ptr = (float*)p;
    cudaGetSymbolAddress(&p, g_att); __half* att_ptr = (__half*)p;

    // 1) QKV projection (fp16 tensor cores, f32 A converted in-kernel)
    {
        dim3 grid((NH + 2 * NKV) * ND / 128, NB * NS / 128);
        h16gemm_nt<float><<<grid, 256>>>(hidden, w_qkv, qkv_ptr,
                                         NB * NS, (NH + 2 * NKV) * ND, NE);
    }

    // 2) RMSNorm + RoPE + cache scatter (fp16 outputs)
    norm_rope_kernel<<<NB * NS, 512>>>(fcos, fsin, kvidx, qnw, knw);

    // 3) sliding-window flash attention (fp16 m16n8k16)
    {
        size_t smem = (size_t)(2 * 64 * QP2 + 256 * VTP + 64 * VTP + 448) * 4;
        cudaFuncSetAttribute(attn_mma_kernel,
                             cudaFuncAttributeMaxDynamicSharedMemorySize,
                             (int)smem);
        dim3 grid(NS / 64, NH, NB);
        attn_mma_kernel<<<grid, 256, smem>>>();
    }

    // 4) output projection (fp16 tensor cores, half A direct)
    {
        dim3 grid(NE / 128, NB * NS / 128);
        h16gemm_nt<__half><<<grid, 256>>>(att_ptr, w_o, out, NB * NS, NE, NH * ND);
    }
}

// round 9
// speedup vs baseline: 2.0182x; 1.8000x over previous
#include <cuda_runtime.h>
#include <cuda_fp16.h>
#include <math.h>

#define NB   2
#define NS   4096
#define NE   2560
#define NH   8
#define NKV  4
#define ND   256
#define NWIN 1024

// ---------------- scratch (device globals: allocation-free) ----------------
static __device__ float  g_qkv[(size_t)NB * NS * (NH + 2 * NKV) * ND]; // f32
static __device__ __half g_q  [(size_t)NB * NH  * NS * ND];            // fp16
static __device__ __half g_k  [(size_t)NB * NKV * NS * ND];
static __device__ __half g_v  [(size_t)NB * NKV * NS * ND];
static __device__ __half g_att[(size_t)NB * NS * NH * ND];             // fp16

__device__ __forceinline__ unsigned h2u(float x, float y) {
    __half2 h = __floats2half2_rn(x, y);
    return *reinterpret_cast<unsigned*>(&h);
}

__device__ __forceinline__ void mma_f16(float* d,
        unsigned a0, unsigned a1, unsigned a2, unsigned a3,
        unsigned b0, unsigned b1) {
    asm volatile(
        "mma.sync.aligned.m16n8k16.row.col.f32.f16.f16.f32 "
        "{%0,%1,%2,%3},{%4,%5,%6,%7},{%8,%9},{%0,%1,%2,%3};"
        : "+f"(d[0]), "+f"(d[1]), "+f"(d[2]), "+f"(d[3])
        : "r"(a0), "r"(a1), "r"(a2), "r"(a3), "r"(b0), "r"(b1));
}

// ---------------------------------------------------------------------------
// FP16 tensor-core GEMM: C[M,N] = A[M,K] @ B[N,K]^T  (row-major, K contig)
// 128x128 tile, BK=64, 256 threads (8 warps, 64x32 each), m16n8k16.
// Coalesced linear-index loaders (16 lanes span one 256B row segment).
// ---------------------------------------------------------------------------
#define GP 36  // smem pitch in uints; 36 % 32 == 4 -> conflict-free frag reads

template<typename TA>
__global__ __launch_bounds__(256, 1) void h16gemm_nt(
        const TA* __restrict__ A, const float* __restrict__ Bm,
        float* __restrict__ C, int M, int N, int K)
{
    constexpr bool AHALF = (sizeof(TA) == 2);
    __shared__ unsigned As[128 * GP];
    __shared__ unsigned Bs[128 * GP];

    int tid  = threadIdx.x;
    int lane = tid & 31;
    int warp = tid >> 5;
    int wm = (warp & 1) * 64;
    int wn = (warp >> 1) * 32;

    const TA*    Ab = A  + (size_t)blockIdx.y * 128 * K;
    const float* Bb = Bm + (size_t)blockIdx.x * 128 * K;

    // prefetch registers
    float4 pa[8]; uint4 ha[4]; float4 pb[8];
    if (AHALF) {
#pragma unroll
        for (int i = 0; i < 4; i++) {
            int f = i * 256 + tid;          // uint4 id: row=f>>3, 8 uint4/row
            ha[i] = *(const uint4*)((const __half*)Ab + (size_t)(f >> 3) * K + (f & 7) * 8);
        }
    } else {
#pragma unroll
        for (int i = 0; i < 8; i++) {
            int f = i * 256 + tid;          // float4 id: row=f>>4, 16 float4/row
            pa[i] = *(const float4*)((const float*)Ab + (size_t)(f >> 4) * K + (f & 15) * 4);
        }
    }
#pragma unroll
    for (int i = 0; i < 8; i++) {
        int f = i * 256 + tid;
        pb[i] = *(const float4*)(Bb + (size_t)(f >> 4) * K + (f & 15) * 4);
    }

    float acc[16][4];
#pragma unroll
    for (int t = 0; t < 16; t++)
#pragma unroll
        for (int e = 0; e < 4; e++) acc[t][e] = 0.0f;

    int fr = lane >> 2;
    int fc = lane & 3;

    for (int k0 = 0; k0 < K; k0 += 64) {
        // commit prefetched chunk to smem
        if (AHALF) {
#pragma unroll
            for (int i = 0; i < 4; i++) {
                int f = i * 256 + tid;
                *(uint4*)&As[(f >> 3) * GP + (f & 7) * 4] = ha[i];
            }
        } else {
#pragma unroll
            for (int i = 0; i < 8; i++) {
                int f = i * 256 + tid;
                uint2 u;
                u.x = h2u(pa[i].x, pa[i].y);
                u.y = h2u(pa[i].z, pa[i].w);
                *(uint2*)&As[(f >> 4) * GP + (f & 15) * 2] = u;
            }
        }
#pragma unroll
        for (int i = 0; i < 8; i++) {
            int f = i * 256 + tid;
            uint2 u;
            u.x = h2u(pb[i].x, pb[i].y);
            u.y = h2u(pb[i].z, pb[i].w);
            *(uint2*)&Bs[(f >> 4) * GP + (f & 15) * 2] = u;
        }
        __syncthreads();

        if (k0 + 64 < K) {
            if (AHALF) {
#pragma unroll
                for (int i = 0; i < 4; i++) {
                    int f = i * 256 + tid;
                    ha[i] = *(const uint4*)((const __half*)Ab + (size_t)(f >> 3) * K + k0 + 64 + (f & 7) * 8);
                }
            } else {
#pragma unroll
                for (int i = 0; i < 8; i++) {
                    int f = i * 256 + tid;
                    pa[i] = *(const float4*)((const float*)Ab + (size_t)(f >> 4) * K + k0 + 64 + (f & 15) * 4);
                }
            }
#pragma unroll
            for (int i = 0; i < 8; i++) {
                int f = i * 256 + tid;
                pb[i] = *(const float4*)(Bb + (size_t)(f >> 4) * K + k0 + 64 + (f & 15) * 4);
            }
        }

#pragma unroll
        for (int ks = 0; ks < 4; ks++) {
            int ku = ks * 8;
            unsigned af[4][4], bf[4][2];
#pragma unroll
            for (int i = 0; i < 4; i++) {
                int m = wm + i * 16 + fr;
                af[i][0] = As[m * GP + ku + fc];
                af[i][1] = As[(m + 8) * GP + ku + fc];
                af[i][2] = As[m * GP + ku + fc + 4];
                af[i][3] = As[(m + 8) * GP + ku + fc + 4];
            }
#pragma unroll
            for (int j = 0; j < 4; j++) {
                int n = wn + j * 8 + fr;
                bf[j][0] = Bs[n * GP + ku + fc];
                bf[j][1] = Bs[n * GP + ku + fc + 4];
            }
#pragma unroll
            for (int i = 0; i < 4; i++)
#pragma unroll
                for (int j = 0; j < 4; j++)
                    mma_f16(acc[i * 4 + j], af[i][0], af[i][1], af[i][2], af[i][3],
                            bf[j][0], bf[j][1]);
        }
        __syncthreads();
    }

    int c2 = (lane & 3) * 2;
#pragma unroll
    for (int i = 0; i < 4; i++) {
        size_t row0 = (size_t)blockIdx.y * 128 + wm + i * 16 + fr;
#pragma unroll
        for (int j = 0; j < 4; j++) {
            float* d = acc[i * 4 + j];
            size_t col = (size_t)blockIdx.x * 128 + wn + j * 8 + c2;
            *(float2*)&C[row0 * N + col]       = make_float2(d[0], d[1]);
            *(float2*)&C[(row0 + 8) * N + col] = make_float2(d[2], d[3]);
        }
    }
}

// ---------------------------------------------------------------------------
// RMSNorm + RoPE + scatter into fp16 q/k/v buffers.
// ---------------------------------------------------------------------------
__global__ __launch_bounds__(512) void norm_rope_kernel(
        const float* __restrict__ fcos, const float* __restrict__ fsin,
        const int*   __restrict__ kvidx,
        const float* __restrict__ qw, const float* __restrict__ kw)
{
    int token = blockIdx.x;
    int b = token / NS;
    int s = token - b * NS;
    int warp = threadIdx.x >> 5;
    int lane = threadIdx.x & 31;

    const float* src = g_qkv + (size_t)token * ((NH + 2 * NKV) * ND) + warp * ND;

    float x1[4], x2[4];
#pragma unroll
    for (int i = 0; i < 4; i++) {
        x1[i] = src[lane + 32 * i];
        x2[i] = src[128 + lane + 32 * i];
    }

    if (warp >= 12) { // V: copy
        int kh = warp - 12;
        __half* dst = g_v + ((size_t)(b * NKV + kh) * NS + kvidx[s]) * ND;
#pragma unroll
        for (int i = 0; i < 4; i++) {
            dst[lane + 32 * i]       = __float2half(x1[i]);
            dst[128 + lane + 32 * i] = __float2half(x2[i]);
        }
        return;
    }

    float ss = 0.0f;
#pragma unroll
    for (int i = 0; i < 4; i++) ss += x1[i] * x1[i] + x2[i] * x2[i];
#pragma unroll
    for (int m = 16; m; m >>= 1) ss += __shfl_xor_sync(0xffffffffu, ss, m);
    float inv = rsqrtf(ss * (1.0f / ND) + 1e-6f);

    const float* w   = (warp < 8) ? qw : kw;
    float scale      = (warp < 8) ? 0.0625f : 1.0f; // SCALING folded into q
    __half* dst;
    if (warp < 8) dst = g_q + ((size_t)(b * NH + warp) * NS + s) * ND;
    else          dst = g_k + ((size_t)(b * NKV + (warp - 8)) * NS + kvidx[s]) * ND;

#pragma unroll
    for (int i = 0; i < 4; i++) {
        int d = lane + 32 * i;
        float c  = fcos[(size_t)s * 128 + d];
        float sn = fsin[(size_t)s * 128 + d];
        float y1 = x1[i] * inv * (1.0f + w[d]);
        float y2 = x2[i] * inv * (1.0f + w[d + 128]);
        dst[d]       = __float2half((y1 * c - y2 * sn) * scale);
        dst[d + 128] = __float2half((y2 * c + y1 * sn) * scale);
    }
}

// ---------------------------------------------------------------------------
// Sliding-window flash attention, fp16 m16n8k16. BM=BN=64, 256 thr (8 warps).
// QK: warp (wr,wc): rows 16wr.., keys 32wc.. (4 n-tiles), k=256.
// Softmax fully in registers; only pmax/psum scalars + fp16 probs hit smem.
// PV: warp owns d-slice [32*warp,+32) over all 64 rows, k=64 (V transposed).
// ---------------------------------------------------------------------------
#define QP2 132   // Q/K pitch in uints (256 halves = 128 uints + pad)
#define VTP 36    // Vt/Pp pitch in uints (64 halves = 32 uints + pad)

__global__ __launch_bounds__(256, 1) void attn_mma_kernel()
{
    extern __shared__ unsigned smu[];
    unsigned* Qs = smu;                    // [64][QP2]
    unsigned* Ks = Qs + 64 * QP2;          // [64][QP2]
    unsigned* Vt = Ks + 64 * QP2;          // [256][VTP]  (d-major, key half2)
    unsigned* Pp = Vt + 256 * VTP;         // [64][VTP]   fp16 probs
    float* pmax = (float*)(Pp + 64 * VTP); // [64][2]
    float* psum = pmax + 128;              // [64][2]
    float* ms   = psum + 128;              // [64]
    float* ls   = ms + 64;                 // [64]
    float* cs   = ls + 64;                 // [64]

    int qt = blockIdx.x, h = blockIdx.y, b = blockIdx.z;
    int q0 = qt * 64;
    int kh = h >> 1;

    const unsigned* Qg = (const unsigned*)(g_q + ((size_t)(b * NH + h) * NS + q0) * ND);
    const unsigned* Kg = (const unsigned*)(g_k + (size_t)(b * NKV + kh) * NS * ND);
    const unsigned* Vg = (const unsigned*)(g_v + (size_t)(b * NKV + kh) * NS * ND);

    int tid  = threadIdx.x;
    int lane = tid & 31;
    int warp = tid >> 5;
    int wr = warp & 3;
    int wc = warp >> 2;
    int fr = lane >> 2;
    int fc = lane & 3;

    // Q tile: raw copy (row = 128 uints)
    for (int i = tid; i < 64 * 32; i += 256) {
        int r = i >> 5, c4 = (i & 31) * 4;
        *(uint4*)&Qs[r * QP2 + c4] = *(const uint4*)(Qg + (size_t)r * 128 + c4);
    }
    if (tid < 64) { ms[tid] = -1e30f; ls[tid] = 0.0f; }

    float oacc[16][4];
#pragma unroll
    for (int t = 0; t < 16; t++)
#pragma unroll
        for (int e = 0; e < 4; e++) oacc[t][e] = 0.0f;

    int t0 = qt - 16; if (t0 < 0) t0 = 0;
    int r0 = 16 * wr + fr;

    for (int kt = t0; kt <= qt; kt++) {
        int k0 = kt * 64;
        __syncthreads(); // A: prev PV done, buffers free

        // K tile copy
        for (int i = tid; i < 64 * 32; i += 256) {
            int r = i >> 5, c4 = (i & 31) * 4;
            *(uint4*)&Ks[r * QP2 + c4] = *(const uint4*)(Kg + (size_t)(k0 + r) * 128 + c4);
        }
        // V tile transposed: tasks = 32 keypairs x 32 d-chunks
#pragma unroll
        for (int t = 0; t < 4; t++) {
            int task = tid + 256 * t;
            int kp = task & 31;        // key pair index
            int dch = task >> 5;       // d chunk (8 halves)
            uint4 va = *(const uint4*)(Vg + (size_t)(k0 + 2 * kp)     * 128 + dch * 4);
            uint4 vb = *(const uint4*)(Vg + (size_t)(k0 + 2 * kp + 1) * 128 + dch * 4);
            int d0 = dch * 8;
            unsigned au[4] = {va.x, va.y, va.z, va.w};
            unsigned bu[4] = {vb.x, vb.y, vb.z, vb.w};
#pragma unroll
            for (int j = 0; j < 4; j++) {
                Vt[(d0 + 2 * j)     * VTP + kp] = __byte_perm(au[j], bu[j], 0x5410);
                Vt[(d0 + 2 * j + 1) * VTP + kp] = __byte_perm(au[j], bu[j], 0x7632);
            }
        }
        __syncthreads(); // B: K, Vt ready

        // ---- scores: m16 x n32 per warp, k=256 (16 k16 steps) ----
        float sacc[4][4];
#pragma unroll
        for (int t = 0; t < 4; t++)
#pragma unroll
            for (int e = 0; e < 4; e++) sacc[t][e] = 0.0f;

#pragma unroll 4
        for (int ku = 0; ku < 128; ku += 8) {
            unsigned a0 = Qs[r0 * QP2 + ku + fc];
            unsigned a1 = Qs[(r0 + 8) * QP2 + ku + fc];
            unsigned a2 = Qs[r0 * QP2 + ku + fc + 4];
            unsigned a3 = Qs[(r0 + 8) * QP2 + ku + fc + 4];
#pragma unroll
            for (int nt = 0; nt < 4; nt++) {
                int n = 32 * wc + 8 * nt + fr;
                unsigned b0 = Ks[n * QP2 + ku + fc];
                unsigned b1 = Ks[n * QP2 + ku + fc + 4];
                mma_f16(sacc[nt], a0, a1, a2, a3, b0, b1);
            }
        }

        // softcap + mask in registers; per-row partial max
        float mx0 = -1e30f, mx1 = -1e30f;
#pragma unroll
        for (int nt = 0; nt < 4; nt++) {
#pragma unroll
            for (int e = 0; e < 4; e++) {
                int r  = r0 + (e >> 1) * 8;
                int kj = k0 + 32 * wc + 8 * nt + 2 * fc + (e & 1);
                int qi = q0 + r;
                float ev = __expf(sacc[nt][e] * 0.04f);
                float v = 50.0f - 100.0f / (ev + 1.0f);
                bool ok = (kj <= qi) && (qi - kj < NWIN);
                v = ok ? v : -1e30f;
                sacc[nt][e] = v;
                if ((e >> 1) == 0) mx0 = fmaxf(mx0, v); else mx1 = fmaxf(mx1, v);
            }
        }
        mx0 = fmaxf(mx0, __shfl_xor_sync(0xffffffffu, mx0, 1));
        mx0 = fmaxf(mx0, __shfl_xor_sync(0xffffffffu, mx0, 2));
        mx1 = fmaxf(mx1, __shfl_xor_sync(0xffffffffu, mx1, 1));
        mx1 = fmaxf(mx1, __shfl_xor_sync(0xffffffffu, mx1, 2));
        if (fc == 0) {
            pmax[r0 * 2 + wc]       = mx0;
            pmax[(r0 + 8) * 2 + wc] = mx1;
        }
        __syncthreads(); // C: pmax complete

        // ---- P phase: probs + partial sums + m/cs update ----
        {
            float mo0 = ms[r0];
            float mo1 = ms[r0 + 8];
            float mn0 = fmaxf(mo0, fmaxf(pmax[r0 * 2], pmax[r0 * 2 + 1]));
            float mn1 = fmaxf(mo1, fmaxf(pmax[(r0 + 8) * 2], pmax[(r0 + 8) * 2 + 1]));
            if (wc == 0 && fc == 0) {
                cs[r0]     = __expf(mo0 - mn0);
                cs[r0 + 8] = __expf(mo1 - mn1);
                ms[r0]     = mn0;   // benign race: later readers get same max
                ms[r0 + 8] = mn1;
            }
            float rs0 = 0.0f, rs1 = 0.0f;
#pragma unroll
            for (int nt = 0; nt < 4; nt++) {
                float p0 = __expf(sacc[nt][0] - mn0);
                float p1 = __expf(sacc[nt][1] - mn0);
                float p2 = __expf(sacc[nt][2] - mn1);
                float p3 = __expf(sacc[nt][3] - mn1);
                rs0 += p0 + p1; rs1 += p2 + p3;
                int cu = 16 * wc + 4 * nt + fc;
                Pp[r0 * VTP + cu]       = h2u(p0, p1);
                Pp[(r0 + 8) * VTP + cu] = h2u(p2, p3);
            }
            rs0 += __shfl_xor_sync(0xffffffffu, rs0, 1);
            rs0 += __shfl_xor_sync(0xffffffffu, rs0, 2);
            rs1 += __shfl_xor_sync(0xffffffffu, rs1, 1);
            rs1 += __shfl_xor_sync(0xffffffffu, rs1, 2);
            if (fc == 0) {
                psum[r0 * 2 + wc]       = rs0;
                psum[(r0 + 8) * 2 + wc] = rs1;
            }
        }
        __syncthreads(); // D: probs + psum + cs visible

        // ---- PV phase: l update, O rescale, O += P @ V ----
        if (tid < 64)
            ls[tid] = ls[tid] * cs[tid] + psum[tid * 2] + psum[tid * 2 + 1];
        {
            float cr0[4], cr1[4];
#pragma unroll
            for (int mt = 0; mt < 4; mt++) {
                cr0[mt] = cs[16 * mt + fr];
                cr1[mt] = cs[16 * mt + fr + 8];
            }
#pragma unroll
            for (int mt = 0; mt < 4; mt++)
#pragma unroll
                for (int nt = 0; nt < 4; nt++) {
                    float* d = oacc[mt * 4 + nt];
                    d[0] *= cr0[mt]; d[1] *= cr0[mt];
                    d[2] *= cr1[mt]; d[3] *= cr1[mt];
                }
#pragma unroll
            for (int ku = 0; ku < 32; ku += 8) {
                unsigned pa[4][4];
#pragma unroll
                for (int mt = 0; mt < 4; mt++) {
                    int r = 16 * mt + fr;
                    pa[mt][0] = Pp[r * VTP + ku + fc];
                    pa[mt][1] = Pp[(r + 8) * VTP + ku + fc];
                    pa[mt][2] = Pp[r * VTP + ku + fc + 4];
                    pa[mt][3] = Pp[(r + 8) * VTP + ku + fc + 4];
                }
                unsigned vb[4][2];
#pragma unroll
                for (int nt = 0; nt < 4; nt++) {
                    int dn = 32 * warp + 8 * nt + fr;
                    vb[nt][0] = Vt[dn * VTP + ku + fc];
                    vb[nt][1] = Vt[dn * VTP + ku + fc + 4];
                }
#pragma unroll
                for (int mt = 0; mt < 4; mt++)
#pragma unroll
                    for (int nt = 0; nt < 4; nt++)
                        mma_f16(oacc[mt * 4 + nt], pa[mt][0], pa[mt][1], pa[mt][2], pa[mt][3],
                                vb[nt][0], vb[nt][1]);
            }
        }
    }
    __syncthreads(); // final ls values visible

    // epilogue: write fp16 att output [b, s, h*D + d]
    {
        unsigned* Og = (unsigned*)(g_att + ((size_t)b * NS + q0) * (NH * ND) + h * ND);
#pragma unroll
        for (int mt = 0; mt < 4; mt++) {
            int r = 16 * mt + fr;
            float il0 = 1.0f / ls[r];
            float il1 = 1.0f / ls[r + 8];
#pragma unroll
            for (int nt = 0; nt < 4; nt++) {
                float* d = oacc[mt * 4 + nt];
                int cu = 16 * warp + 4 * nt + fc; // uint col within head slice
                Og[(size_t)r * 1024 + cu]       = h2u(d[0] * il0, d[1] * il0);
                Og[(size_t)(r + 8) * 1024 + cu] = h2u(d[2] * il1, d[3] * il1);
            }
        }
    }
}

// ---------------------------------------------------------------------------
extern "C" void kernel_launch(void* const* d_in, const int* in_sizes, int n_in,
                              void* d_out, int out_size)
{
    const float* hidden = (const float*)d_in[0];
    const float* fcos   = (const float*)d_in[1];
    const float* fsin   = (const float*)d_in[2];
    const int*   kvidx  = (const int*)  d_in[3];
    const float* w_qkv  = (const float*)d_in[8];
    const float* w_o    = (const float*)d_in[9];
    const float* qnw    = (const float*)d_in[10];
    const float* knw    = (const float*)d_in[11];
    float* out = (float*)d_out;

    void* p;
    cudaGetSymbolAddress(&p, g_qkv); float*  qkv_ptr = (float*)p;
    cudaGetSymbolAddress(&p, g_att); __half* att_ptr = (__half*)p;

    // 1) QKV projection (fp16 tensor cores, f32 A converted in-kernel)
    {
        dim3 grid((NH + 2 * NKV) * ND / 128, NB * NS / 128);
        h16gemm_nt<float><<<grid, 256>>>(hidden, w_qkv, qkv_ptr,
                                         NB * NS, (NH + 2 * NKV) * ND, NE);
    }

    // 2) RMSNorm + RoPE + cache scatter (fp16 outputs)
    norm_rope_kernel<<<NB * NS, 512>>>(fcos, fsin, kvidx, qnw, knw);

    // 3) sliding-window flash attention (fp16 m16n8k16)
    {
        size_t smem = (size_t)(2 * 64 * QP2 + 256 * VTP + 64 * VTP + 448) * 4;
        cudaFuncSetAttribute(attn_mma_kernel,
                             cudaFuncAttributeMaxDynamicSharedMemorySize,
                             (int)smem);
        dim3 grid(NS / 64, NH, NB);
        attn_mma_kernel<<<grid, 256, smem>>>();
    }

    // 4) output projection (fp16 tensor cores, half A direct)
    {
        dim3 grid(NE / 128, NB * NS / 128);
        h16gemm_nt<__half><<<grid, 256>>>(att_ptr, w_o, out, NB * NS, NE, NH * ND);
    }
}

// round 10
// speedup vs baseline: 2.2252x; 1.1025x over previous
#include <cuda_runtime.h>
#include <cuda_fp16.h>
#include <math.h>

#define NB   2
#define NS   4096
#define NE   2560
#define NH   8
#define NKV  4
#define ND   256
#define NWIN 1024

// ---------------- scratch (device globals: allocation-free) ----------------
static __device__ float  g_qkv[(size_t)NB * NS * (NH + 2 * NKV) * ND]; // f32
static __device__ __half g_q  [(size_t)NB * NH  * NS * ND];            // fp16
static __device__ __half g_k  [(size_t)NB * NKV * NS * ND];
static __device__ __half g_v  [(size_t)NB * NKV * NS * ND];
static __device__ __half g_att[(size_t)NB * NS * NH * ND];             // fp16

__device__ __forceinline__ unsigned h2u(float x, float y) {
    __half2 h = __floats2half2_rn(x, y);
    return *reinterpret_cast<unsigned*>(&h);
}

__device__ __forceinline__ void mma_f16(float* d,
        unsigned a0, unsigned a1, unsigned a2, unsigned a3,
        unsigned b0, unsigned b1) {
    asm volatile(
        "mma.sync.aligned.m16n8k16.row.col.f32.f16.f16.f32 "
        "{%0,%1,%2,%3},{%4,%5,%6,%7},{%8,%9},{%0,%1,%2,%3};"
        : "+f"(d[0]), "+f"(d[1]), "+f"(d[2]), "+f"(d[3])
        : "r"(a0), "r"(a1), "r"(a2), "r"(a3), "r"(b0), "r"(b1));
}

__device__ __forceinline__ void ldsm4(unsigned& r0, unsigned& r1,
                                      unsigned& r2, unsigned& r3, unsigned a) {
    asm volatile("ldmatrix.sync.aligned.m8n8.x4.shared.b16 {%0,%1,%2,%3}, [%4];"
                 : "=r"(r0), "=r"(r1), "=r"(r2), "=r"(r3) : "r"(a));
}
__device__ __forceinline__ void ldsm4t(unsigned& r0, unsigned& r1,
                                       unsigned& r2, unsigned& r3, unsigned a) {
    asm volatile("ldmatrix.sync.aligned.m8n8.x4.trans.shared.b16 {%0,%1,%2,%3}, [%4];"
                 : "=r"(r0), "=r"(r1), "=r"(r2), "=r"(r3) : "r"(a));
}

// ---------------------------------------------------------------------------
// FP16 tensor-core GEMM: C[M,N] = A[M,K] @ B[N,K]^T  (row-major, K contig)
// 128x128 tile, BK=64, 256 threads (8 warps, 64x32 each), m16n8k16 + ldmatrix.
// ---------------------------------------------------------------------------
#define GP 36  // smem pitch in uints; 36 % 32 == 4 -> conflict-free LDSM rows

template<typename TA>
__global__ __launch_bounds__(256, 1) void h16gemm_nt(
        const TA* __restrict__ A, const float* __restrict__ Bm,
        float* __restrict__ C, int M, int N, int K)
{
    constexpr bool AHALF = (sizeof(TA) == 2);
    __shared__ unsigned As[128 * GP];
    __shared__ unsigned Bs[128 * GP];

    int tid  = threadIdx.x;
    int lane = tid & 31;
    int warp = tid >> 5;
    int wm = (warp & 1) * 64;
    int wn = (warp >> 1) * 32;

    const TA*    Ab = A  + (size_t)blockIdx.y * 128 * K;
    const float* Bb = Bm + (size_t)blockIdx.x * 128 * K;

    // coalesced prefetch (round-9 proven mapping)
    float4 pa[8]; uint4 ha[4]; float4 pb[8];
    if (AHALF) {
#pragma unroll
        for (int i = 0; i < 4; i++) {
            int f = i * 256 + tid;
            ha[i] = *(const uint4*)((const __half*)Ab + (size_t)(f >> 3) * K + (f & 7) * 8);
        }
    } else {
#pragma unroll
        for (int i = 0; i < 8; i++) {
            int f = i * 256 + tid;
            pa[i] = *(const float4*)((const float*)Ab + (size_t)(f >> 4) * K + (f & 15) * 4);
        }
    }
#pragma unroll
    for (int i = 0; i < 8; i++) {
        int f = i * 256 + tid;
        pb[i] = *(const float4*)(Bb + (size_t)(f >> 4) * K + (f & 15) * 4);
    }

    float acc[16][4];
#pragma unroll
    for (int t = 0; t < 16; t++)
#pragma unroll
        for (int e = 0; e < 4; e++) acc[t][e] = 0.0f;

    int fr = lane >> 2;
    int r8 = lane & 7, quad = lane >> 3;
    unsigned asmb = (unsigned)__cvta_generic_to_shared(As);
    unsigned bsmb = (unsigned)__cvta_generic_to_shared(Bs);
    // A frag: quad0: (m+r8, kblk0) q1: (m+8+r8, kblk0) q2: (m+r8, kblk1) q3: (+8, kblk1)
    unsigned aOff = asmb + (((wm + (quad & 1) * 8 + r8) * GP + (quad >> 1) * 4) << 2);
    // B pair: quad0: (n+r8, kb0) q1: (n+r8, kb1) q2: (n+8+r8, kb0) q3: (n+8, kb1)
    unsigned bOff = bsmb + (((wn + (quad >> 1) * 8 + r8) * GP + (quad & 1) * 4) << 2);

    for (int k0 = 0; k0 < K; k0 += 64) {
        if (AHALF) {
#pragma unroll
            for (int i = 0; i < 4; i++) {
                int f = i * 256 + tid;
                *(uint4*)&As[(f >> 3) * GP + (f & 7) * 4] = ha[i];
            }
        } else {
#pragma unroll
            for (int i = 0; i < 8; i++) {
                int f = i * 256 + tid;
                uint2 u;
                u.x = h2u(pa[i].x, pa[i].y);
                u.y = h2u(pa[i].z, pa[i].w);
                *(uint2*)&As[(f >> 4) * GP + (f & 15) * 2] = u;
            }
        }
#pragma unroll
        for (int i = 0; i < 8; i++) {
            int f = i * 256 + tid;
            uint2 u;
            u.x = h2u(pb[i].x, pb[i].y);
            u.y = h2u(pb[i].z, pb[i].w);
            *(uint2*)&Bs[(f >> 4) * GP + (f & 15) * 2] = u;
        }
        __syncthreads();

        if (k0 + 64 < K) {
            if (AHALF) {
#pragma unroll
                for (int i = 0; i < 4; i++) {
                    int f = i * 256 + tid;
                    ha[i] = *(const uint4*)((const __half*)Ab + (size_t)(f >> 3) * K + k0 + 64 + (f & 7) * 8);
                }
            } else {
#pragma unroll
                for (int i = 0; i < 8; i++) {
                    int f = i * 256 + tid;
                    pa[i] = *(const float4*)((const float*)Ab + (size_t)(f >> 4) * K + k0 + 64 + (f & 15) * 4);
                }
            }
#pragma unroll
            for (int i = 0; i < 8; i++) {
                int f = i * 256 + tid;
                pb[i] = *(const float4*)(Bb + (size_t)(f >> 4) * K + k0 + 64 + (f & 15) * 4);
            }
        }

#pragma unroll
        for (int ks = 0; ks < 4; ks++) {
            unsigned kb = ks * 32;   // 8 uints per k16 step
            unsigned af[4][4], bf[4][2];
#pragma unroll
            for (int i = 0; i < 4; i++)
                ldsm4(af[i][0], af[i][1], af[i][2], af[i][3],
                      aOff + i * (16 * GP * 4) + kb);
            ldsm4(bf[0][0], bf[0][1], bf[1][0], bf[1][1], bOff + kb);
            ldsm4(bf[2][0], bf[2][1], bf[3][0], bf[3][1], bOff + 16 * GP * 4 + kb);
#pragma unroll
            for (int i = 0; i < 4; i++)
#pragma unroll
                for (int j = 0; j < 4; j++)
                    mma_f16(acc[i * 4 + j], af[i][0], af[i][1], af[i][2], af[i][3],
                            bf[j][0], bf[j][1]);
        }
        __syncthreads();
    }

    int c2 = (lane & 3) * 2;
#pragma unroll
    for (int i = 0; i < 4; i++) {
        size_t row0 = (size_t)blockIdx.y * 128 + wm + i * 16 + fr;
#pragma unroll
        for (int j = 0; j < 4; j++) {
            float* d = acc[i * 4 + j];
            size_t col = (size_t)blockIdx.x * 128 + wn + j * 8 + c2;
            *(float2*)&C[row0 * N + col]       = make_float2(d[0], d[1]);
            *(float2*)&C[(row0 + 8) * N + col] = make_float2(d[2], d[3]);
        }
    }
}

// ---------------------------------------------------------------------------
// RMSNorm + RoPE + scatter into fp16 q/k/v buffers.
// ---------------------------------------------------------------------------
__global__ __launch_bounds__(512) void norm_rope_kernel(
        const float* __restrict__ fcos, const float* __restrict__ fsin,
        const int*   __restrict__ kvidx,
        const float* __restrict__ qw, const float* __restrict__ kw)
{
    int token = blockIdx.x;
    int b = token / NS;
    int s = token - b * NS;
    int warp = threadIdx.x >> 5;
    int lane = threadIdx.x & 31;

    const float* src = g_qkv + (size_t)token * ((NH + 2 * NKV) * ND) + warp * ND;

    float x1[4], x2[4];
#pragma unroll
    for (int i = 0; i < 4; i++) {
        x1[i] = src[lane + 32 * i];
        x2[i] = src[128 + lane + 32 * i];
    }

    if (warp >= 12) { // V: copy
        int kh = warp - 12;
        __half* dst = g_v + ((size_t)(b * NKV + kh) * NS + kvidx[s]) * ND;
#pragma unroll
        for (int i = 0; i < 4; i++) {
            dst[lane + 32 * i]       = __float2half(x1[i]);
            dst[128 + lane + 32 * i] = __float2half(x2[i]);
        }
        return;
    }

    float ss = 0.0f;
#pragma unroll
    for (int i = 0; i < 4; i++) ss += x1[i] * x1[i] + x2[i] * x2[i];
#pragma unroll
    for (int m = 16; m; m >>= 1) ss += __shfl_xor_sync(0xffffffffu, ss, m);
    float inv = rsqrtf(ss * (1.0f / ND) + 1e-6f);

    const float* w   = (warp < 8) ? qw : kw;
    float scale      = (warp < 8) ? 0.0625f : 1.0f; // SCALING folded into q
    __half* dst;
    if (warp < 8) dst = g_q + ((size_t)(b * NH + warp) * NS + s) * ND;
    else          dst = g_k + ((size_t)(b * NKV + (warp - 8)) * NS + kvidx[s]) * ND;

#pragma unroll
    for (int i = 0; i < 4; i++) {
        int d = lane + 32 * i;
        float c  = fcos[(size_t)s * 128 + d];
        float sn = fsin[(size_t)s * 128 + d];
        float y1 = x1[i] * inv * (1.0f + w[d]);
        float y2 = x2[i] * inv * (1.0f + w[d + 128]);
        dst[d]       = __float2half((y1 * c - y2 * sn) * scale);
        dst[d + 128] = __float2half((y2 * c + y1 * sn) * scale);
    }
}

// ---------------------------------------------------------------------------
// Sliding-window flash attention, fp16 m16n8k16 + ldmatrix.
// BM=BN=64, 256 thr (8 warps). V read via ldmatrix.trans (no transpose pass).
// QK: warp (wr,wc): rows 16wr.., keys 32wc.. (4 n-tiles), k=256.
// PV: warp owns d-slice [32*warp,+32) over all 64 rows, k=64.
// ---------------------------------------------------------------------------
#define QP2 132   // Q/K/V pitch in uints (256 halves = 128 uints + pad)
#define VTP 36    // Pp pitch in uints (64 halves = 32 uints + pad)

__global__ __launch_bounds__(256, 1) void attn_mma_kernel()
{
    extern __shared__ unsigned smu[];
    unsigned* Qs = smu;                    // [64][QP2]
    unsigned* Ks = Qs + 64 * QP2;          // [64][QP2]
    unsigned* Vs = Ks + 64 * QP2;          // [64][QP2]  (natural layout)
    unsigned* Pp = Vs + 64 * QP2;          // [64][VTP]  fp16 probs
    float* pmax = (float*)(Pp + 64 * VTP); // [64][2]
    float* psum = pmax + 128;              // [64][2]
    float* ms   = psum + 128;              // [64]
    float* ls   = ms + 64;                 // [64]
    float* cs   = ls + 64;                 // [64]

    int qt = blockIdx.x, h = blockIdx.y, b = blockIdx.z;
    int q0 = qt * 64;
    int kh = h >> 1;

    const unsigned* Qg = (const unsigned*)(g_q + ((size_t)(b * NH + h) * NS + q0) * ND);
    const unsigned* Kg = (const unsigned*)(g_k + (size_t)(b * NKV + kh) * NS * ND);
    const unsigned* Vg = (const unsigned*)(g_v + (size_t)(b * NKV + kh) * NS * ND);

    int tid  = threadIdx.x;
    int lane = tid & 31;
    int warp = tid >> 5;
    int wr = warp & 3;
    int wc = warp >> 2;
    int fr = lane >> 2;
    int fc = lane & 3;
    int r8 = lane & 7, quad = lane >> 3;

    unsigned qsm = (unsigned)__cvta_generic_to_shared(Qs);
    unsigned ksm = (unsigned)__cvta_generic_to_shared(Ks);
    unsigned vsm = (unsigned)__cvta_generic_to_shared(Vs);
    unsigned psm = (unsigned)__cvta_generic_to_shared(Pp);

    // ldmatrix base offsets
    unsigned qOff = qsm + (((16 * wr + (quad & 1) * 8 + r8) * QP2 + (quad >> 1) * 4) << 2);
    unsigned kOff = ksm + (((32 * wc + (quad >> 1) * 8 + r8) * QP2 + (quad & 1) * 4) << 2);
    unsigned pOff = psm + ((((quad & 1) * 8 + r8) * VTP + (quad >> 1) * 4) << 2);
    unsigned vOff = vsm + ((((quad & 1) * 8 + r8) * QP2 + 16 * warp + (quad >> 1) * 4) << 2);

    // Q tile: raw copy (row = 128 uints)
    for (int i = tid; i < 64 * 32; i += 256) {
        int r = i >> 5, c4 = (i & 31) * 4;
        *(uint4*)&Qs[r * QP2 + c4] = *(const uint4*)(Qg + (size_t)r * 128 + c4);
    }
    if (tid < 64) { ms[tid] = -1e30f; ls[tid] = 0.0f; }

    float oacc[16][4];
#pragma unroll
    for (int t = 0; t < 16; t++)
#pragma unroll
        for (int e = 0; e < 4; e++) oacc[t][e] = 0.0f;

    int t0 = qt - 16; if (t0 < 0) t0 = 0;
    int r0 = 16 * wr + fr;

    for (int kt = t0; kt <= qt; kt++) {
        int k0 = kt * 64;
        __syncthreads(); // A: prev PV done, buffers free

        // K and V tiles, natural layout
        for (int i = tid; i < 64 * 32; i += 256) {
            int r = i >> 5, c4 = (i & 31) * 4;
            *(uint4*)&Ks[r * QP2 + c4] = *(const uint4*)(Kg + (size_t)(k0 + r) * 128 + c4);
            *(uint4*)&Vs[r * QP2 + c4] = *(const uint4*)(Vg + (size_t)(k0 + r) * 128 + c4);
        }
        __syncthreads(); // B: K, V ready

        // ---- scores: m16 x n32 per warp, k=256 (16 k16 steps) ----
        float sacc[4][4];
#pragma unroll
        for (int t = 0; t < 4; t++)
#pragma unroll
            for (int e = 0; e < 4; e++) sacc[t][e] = 0.0f;

#pragma unroll
        for (int ks = 0; ks < 16; ks++) {
            unsigned kb = ks * 32; // 8 uints per step
            unsigned a0, a1, a2, a3;
            ldsm4(a0, a1, a2, a3, qOff + kb);
            unsigned bf[4][2];
            ldsm4(bf[0][0], bf[0][1], bf[1][0], bf[1][1], kOff + kb);
            ldsm4(bf[2][0], bf[2][1], bf[3][0], bf[3][1], kOff + 16 * QP2 * 4 + kb);
#pragma unroll
            for (int nt = 0; nt < 4; nt++)
                mma_f16(sacc[nt], a0, a1, a2, a3, bf[nt][0], bf[nt][1]);
        }

        // softcap + mask in registers; per-row partial max
        float mx0 = -1e30f, mx1 = -1e30f;
#pragma unroll
        for (int nt = 0; nt < 4; nt++) {
#pragma unroll
            for (int e = 0; e < 4; e++) {
                int r  = r0 + (e >> 1) * 8;
                int kj = k0 + 32 * wc + 8 * nt + 2 * fc + (e & 1);
                int qi = q0 + r;
                float ev = __expf(sacc[nt][e] * 0.04f);
                float v = 50.0f - 100.0f / (ev + 1.0f);
                bool ok = (kj <= qi) && (qi - kj < NWIN);
                v = ok ? v : -1e30f;
                sacc[nt][e] = v;
                if ((e >> 1) == 0) mx0 = fmaxf(mx0, v); else mx1 = fmaxf(mx1, v);
            }
        }
        mx0 = fmaxf(mx0, __shfl_xor_sync(0xffffffffu, mx0, 1));
        mx0 = fmaxf(mx0, __shfl_xor_sync(0xffffffffu, mx0, 2));
        mx1 = fmaxf(mx1, __shfl_xor_sync(0xffffffffu, mx1, 1));
        mx1 = fmaxf(mx1, __shfl_xor_sync(0xffffffffu, mx1, 2));
        if (fc == 0) {
            pmax[r0 * 2 + wc]       = mx0;
            pmax[(r0 + 8) * 2 + wc] = mx1;
        }
        __syncthreads(); // C: pmax complete

        // ---- P phase: probs + partial sums + m/cs update ----
        {
            float mo0 = ms[r0];
            float mo1 = ms[r0 + 8];
            float mn0 = fmaxf(mo0, fmaxf(pmax[r0 * 2], pmax[r0 * 2 + 1]));
            float mn1 = fmaxf(mo1, fmaxf(pmax[(r0 + 8) * 2], pmax[(r0 + 8) * 2 + 1]));
            if (wc == 0 && fc == 0) {
                cs[r0]     = __expf(mo0 - mn0);
                cs[r0 + 8] = __expf(mo1 - mn1);
                ms[r0]     = mn0;   // benign race: same value from both writers
                ms[r0 + 8] = mn1;
            }
            float rs0 = 0.0f, rs1 = 0.0f;
#pragma unroll
            for (int nt = 0; nt < 4; nt++) {
                float p0 = __expf(sacc[nt][0] - mn0);
                float p1 = __expf(sacc[nt][1] - mn0);
                float p2 = __expf(sacc[nt][2] - mn1);
                float p3 = __expf(sacc[nt][3] - mn1);
                rs0 += p0 + p1; rs1 += p2 + p3;
                int cu = 16 * wc + 4 * nt + fc;
                Pp[r0 * VTP + cu]       = h2u(p0, p1);
                Pp[(r0 + 8) * VTP + cu] = h2u(p2, p3);
            }
            rs0 += __shfl_xor_sync(0xffffffffu, rs0, 1);
            rs0 += __shfl_xor_sync(0xffffffffu, rs0, 2);
            rs1 += __shfl_xor_sync(0xffffffffu, rs1, 1);
            rs1 += __shfl_xor_sync(0xffffffffu, rs1, 2);
            if (fc == 0) {
                psum[r0 * 2 + wc]       = rs0;
                psum[(r0 + 8) * 2 + wc] = rs1;
            }
        }
        __syncthreads(); // D: probs + psum + cs visible

        // ---- PV phase: l update, O rescale, O += P @ V ----
        if (tid < 64)
            ls[tid] = ls[tid] * cs[tid] + psum[tid * 2] + psum[tid * 2 + 1];
        {
            float cr0[4], cr1[4];
#pragma unroll
            for (int mt = 0; mt < 4; mt++) {
                cr0[mt] = cs[16 * mt + fr];
                cr1[mt] = cs[16 * mt + fr + 8];
            }
#pragma unroll
            for (int mt = 0; mt < 4; mt++)
#pragma unroll
                for (int nt = 0; nt < 4; nt++) {
                    float* d = oacc[mt * 4 + nt];
                    d[0] *= cr0[mt]; d[1] *= cr0[mt];
                    d[2] *= cr1[mt]; d[3] *= cr1[mt];
                }
#pragma unroll
            for (int s = 0; s < 4; s++) {   // k16 steps over 64 keys
                unsigned pa[4][4];
#pragma unroll
                for (int mt = 0; mt < 4; mt++)
                    ldsm4(pa[mt][0], pa[mt][1], pa[mt][2], pa[mt][3],
                          pOff + mt * (16 * VTP * 4) + s * 32);
                unsigned vb[4][2];
                ldsm4t(vb[0][0], vb[0][1], vb[1][0], vb[1][1],
                       vOff + s * (16 * QP2 * 4));
                ldsm4t(vb[2][0], vb[2][1], vb[3][0], vb[3][1],
                       vOff + s * (16 * QP2 * 4) + 32);
#pragma unroll
                for (int mt = 0; mt < 4; mt++)
#pragma unroll
                    for (int nt = 0; nt < 4; nt++)
                        mma_f16(oacc[mt * 4 + nt], pa[mt][0], pa[mt][1], pa[mt][2], pa[mt][3],
                                vb[nt][0], vb[nt][1]);
            }
        }
    }
    __syncthreads(); // final ls values visible

    // epilogue: write fp16 att output [b, s, h*D + d]
    {
        unsigned* Og = (unsigned*)(g_att + ((size_t)b * NS + q0) * (NH * ND) + h * ND);
#pragma unroll
        for (int mt = 0; mt < 4; mt++) {
            int r = 16 * mt + fr;
            float il0 = 1.0f / ls[r];
            float il1 = 1.0f / ls[r + 8];
#pragma unroll
            for (int nt = 0; nt < 4; nt++) {
                float* d = oacc[mt * 4 + nt];
                int cu = 16 * warp + 4 * nt + fc;
                Og[(size_t)r * 1024 + cu]       = h2u(d[0] * il0, d[1] * il0);
                Og[(size_t)(r + 8) * 1024 + cu] = h2u(d[2] * il1, d[3] * il1);
            }
        }
    }
}

// ---------------------------------------------------------------------------
extern "C" void kernel_launch(void* const* d_in, const int* in_sizes, int n_in,
                              void* d_out, int out_size)
{
    const float* hidden = (const float*)d_in[0];
    const float* fcos   = (const float*)d_in[1];
    const float* fsin   = (const float*)d_in[2];
    const int*   kvidx  = (const int*)  d_in[3];
    const float* w_qkv  = (const float*)d_in[8];
    const float* w_o    = (const float*)d_in[9];
    const float* qnw    = (const float*)d_in[10];
    const float* knw    = (const float*)d_in[11];
    float* out = (float*)d_out;

    void* p;
    cudaGetSymbolAddress(&p, g_qkv); float*  qkv_ptr = (float*)p;
    cudaGetSymbolAddress(&p, g_att); __half* att_ptr = (__half*)p;

    // 1) QKV projection (fp16 tensor cores, f32 A converted in-kernel)
    {
        dim3 grid((NH + 2 * NKV) * ND / 128, NB * NS / 128);
        h16gemm_nt<float><<<grid, 256>>>(hidden, w_qkv, qkv_ptr,
                                         NB * NS, (NH + 2 * NKV) * ND, NE);
    }

    // 2) RMSNorm + RoPE + cache scatter (fp16 outputs)
    norm_rope_kernel<<<NB * NS, 512>>>(fcos, fsin, kvidx, qnw, knw);

    // 3) sliding-window flash attention (fp16 m16n8k16 + ldmatrix)
    {
        size_t smem = (size_t)(3 * 64 * QP2 + 64 * VTP + 448) * 4;
        cudaFuncSetAttribute(attn_mma_kernel,
                             cudaFuncAttributeMaxDynamicSharedMemorySize,
                             (int)smem);
        dim3 grid(NS / 64, NH, NB);
        attn_mma_kernel<<<grid, 256, smem>>>();
    }

    // 4) output projection (fp16 tensor cores, half A direct)
    {
        dim3 grid(NE / 128, NB * NS / 128);
        h16gemm_nt<__half><<<grid, 256>>>(att_ptr, w_o, out, NB * NS, NE, NH * ND);
    }
}

// round 11
// speedup vs baseline: 2.6783x; 1.2036x over previous
#include <cuda_runtime.h>
#include <cuda_fp16.h>
#include <math.h>

#define NB   2
#define NS   4096
#define NE   2560
#define NH   8
#define NKV  4
#define ND   256
#define NWIN 1024

// ---------------- scratch (device globals: allocation-free) ----------------
static __device__ float  g_qkv[(size_t)NB * NS * (NH + 2 * NKV) * ND]; // f32
static __device__ __half g_q  [(size_t)NB * NH  * NS * ND];            // fp16
static __device__ __half g_k  [(size_t)NB * NKV * NS * ND];
static __device__ __half g_v  [(size_t)NB * NKV * NS * ND];
static __device__ __half g_att[(size_t)NB * NS * NH * ND];             // fp16
static __device__ __half g_hh [(size_t)NB * NS * NE];                  // hidden fp16
static __device__ __half g_wq [(size_t)(NH + 2 * NKV) * ND * NE];      // w_qkv fp16
static __device__ __half g_wo [(size_t)NE * NH * ND];                  // w_o fp16

__device__ __forceinline__ unsigned h2u(float x, float y) {
    __half2 h = __floats2half2_rn(x, y);
    return *reinterpret_cast<unsigned*>(&h);
}

__device__ __forceinline__ void mma_f16(float* d,
        unsigned a0, unsigned a1, unsigned a2, unsigned a3,
        unsigned b0, unsigned b1) {
    asm volatile(
        "mma.sync.aligned.m16n8k16.row.col.f32.f16.f16.f32 "
        "{%0,%1,%2,%3},{%4,%5,%6,%7},{%8,%9},{%0,%1,%2,%3};"
        : "+f"(d[0]), "+f"(d[1]), "+f"(d[2]), "+f"(d[3])
        : "r"(a0), "r"(a1), "r"(a2), "r"(a3), "r"(b0), "r"(b1));
}

__device__ __forceinline__ void ldsm4(unsigned& r0, unsigned& r1,
                                      unsigned& r2, unsigned& r3, unsigned a) {
    asm volatile("ldmatrix.sync.aligned.m8n8.x4.shared.b16 {%0,%1,%2,%3}, [%4];"
                 : "=r"(r0), "=r"(r1), "=r"(r2), "=r"(r3) : "r"(a));
}
__device__ __forceinline__ void ldsm4t(unsigned& r0, unsigned& r1,
                                       unsigned& r2, unsigned& r3, unsigned a) {
    asm volatile("ldmatrix.sync.aligned.m8n8.x4.trans.shared.b16 {%0,%1,%2,%3}, [%4];"
                 : "=r"(r0), "=r"(r1), "=r"(r2), "=r"(r3) : "r"(a));
}
__device__ __forceinline__ void cp16(unsigned smem_addr, const void* gptr) {
    asm volatile("cp.async.cg.shared.global [%0], [%1], 16;"
                 :: "r"(smem_addr), "l"(gptr));
}

// ---------------------------------------------------------------------------
// f32 -> f16 bulk convert (float4 granularity)
// ---------------------------------------------------------------------------
__global__ __launch_bounds__(256) void f2h_kernel(
        const float* __restrict__ s, __half* __restrict__ d, int n4)
{
    int i = blockIdx.x * blockDim.x + threadIdx.x;
    if (i < n4) {
        float4 v = ((const float4*)s)[i];
        uint2 u;
        u.x = h2u(v.x, v.y);
        u.y = h2u(v.z, v.w);
        ((uint2*)d)[i] = u;
    }
}

// ---------------------------------------------------------------------------
// Pure-fp16 tensor GEMM: C[M,N] = A[M,K] @ B[N,K]^T, both operands fp16.
// 128x128 tile, BK=64, 256 threads (8 warps, 64x32), m16n8k16 + ldmatrix,
// cp.async double-buffered smem, 2 blocks/SM.
// ---------------------------------------------------------------------------
#define GP 36                 // smem pitch in uints; 36 % 32 == 4
#define ABUF (128 * GP)       // one buffer (uints)

__global__ __launch_bounds__(256, 2) void hgemm_nt(
        const __half* __restrict__ A, const __half* __restrict__ Bm,
        float* __restrict__ C, int M, int N, int K)
{
    extern __shared__ unsigned gsm[];
    unsigned* As = gsm;              // [2][ABUF]
    unsigned* Bs = gsm + 2 * ABUF;   // [2][ABUF]

    int tid  = threadIdx.x;
    int lane = tid & 31;
    int warp = tid >> 5;
    int wm = (warp & 1) * 64;
    int wn = (warp >> 1) * 32;

    const __half* Ab = A  + (size_t)blockIdx.y * 128 * K;
    const __half* Bb = Bm + (size_t)blockIdx.x * 128 * K;

    // loader mapping: per i, row = 32*i + (tid>>3), chunk = tid&7 (16B each)
    int lrow = tid >> 3;
    int lch  = tid & 7;
    unsigned asmb = (unsigned)__cvta_generic_to_shared(As);
    unsigned bsmb = (unsigned)__cvta_generic_to_shared(Bs);
    unsigned aSt = asmb + ((lrow * GP + lch * 4) << 2);
    unsigned bSt = bsmb + ((lrow * GP + lch * 4) << 2);

    float acc[16][4];
#pragma unroll
    for (int t = 0; t < 16; t++)
#pragma unroll
        for (int e = 0; e < 4; e++) acc[t][e] = 0.0f;

    int fr = lane >> 2;
    int r8 = lane & 7, quad = lane >> 3;
    unsigned aOff = asmb + (((wm + (quad & 1) * 8 + r8) * GP + (quad >> 1) * 4) << 2);
    unsigned bOff = bsmb + (((wn + (quad >> 1) * 8 + r8) * GP + (quad & 1) * 4) << 2);

    int nIter = K >> 6;

    // prologue: buf 0, k0 = 0
#pragma unroll
    for (int i = 0; i < 4; i++) {
        size_t go = (size_t)(lrow + 32 * i) * K + lch * 8;
        cp16(aSt + i * (32 * GP * 4), Ab + go);
        cp16(bSt + i * (32 * GP * 4), Bb + go);
    }
    asm volatile("cp.async.commit_group;");

    for (int it = 0; it < nIter; it++) {
        int buf = it & 1;
        if (it + 1 < nIter) {
            unsigned sb = (buf ^ 1) * (ABUF * 4);
            int k0n = (it + 1) << 6;
#pragma unroll
            for (int i = 0; i < 4; i++) {
                size_t go = (size_t)(lrow + 32 * i) * K + k0n + lch * 8;
                cp16(aSt + sb + i * (32 * GP * 4), Ab + go);
                cp16(bSt + sb + i * (32 * GP * 4), Bb + go);
            }
            asm volatile("cp.async.commit_group;");
            asm volatile("cp.async.wait_group 1;");
        } else {
            asm volatile("cp.async.wait_group 0;");
        }
        __syncthreads();

        unsigned bufo = buf * (ABUF * 4);
#pragma unroll
        for (int ks = 0; ks < 4; ks++) {
            unsigned kb = bufo + ks * 32;
            unsigned af[4][4], bf[4][2];
#pragma unroll
            for (int i = 0; i < 4; i++)
                ldsm4(af[i][0], af[i][1], af[i][2], af[i][3],
                      aOff + i * (16 * GP * 4) + kb);
            ldsm4(bf[0][0], bf[0][1], bf[1][0], bf[1][1], bOff + kb);
            ldsm4(bf[2][0], bf[2][1], bf[3][0], bf[3][1], bOff + 16 * GP * 4 + kb);
#pragma unroll
            for (int i = 0; i < 4; i++)
#pragma unroll
                for (int j = 0; j < 4; j++)
                    mma_f16(acc[i * 4 + j], af[i][0], af[i][1], af[i][2], af[i][3],
                            bf[j][0], bf[j][1]);
        }
        __syncthreads();
    }

    int c2 = (lane & 3) * 2;
#pragma unroll
    for (int i = 0; i < 4; i++) {
        size_t row0 = (size_t)blockIdx.y * 128 + wm + i * 16 + fr;
#pragma unroll
        for (int j = 0; j < 4; j++) {
            float* d = acc[i * 4 + j];
            size_t col = (size_t)blockIdx.x * 128 + wn + j * 8 + c2;
            *(float2*)&C[row0 * N + col]       = make_float2(d[0], d[1]);
            *(float2*)&C[(row0 + 8) * N + col] = make_float2(d[2], d[3]);
        }
    }
}

// ---------------------------------------------------------------------------
// RMSNorm + RoPE + scatter into fp16 q/k/v buffers.
// ---------------------------------------------------------------------------
__global__ __launch_bounds__(512) void norm_rope_kernel(
        const float* __restrict__ fcos, const float* __restrict__ fsin,
        const int*   __restrict__ kvidx,
        const float* __restrict__ qw, const float* __restrict__ kw)
{
    int token = blockIdx.x;
    int b = token / NS;
    int s = token - b * NS;
    int warp = threadIdx.x >> 5;
    int lane = threadIdx.x & 31;

    const float* src = g_qkv + (size_t)token * ((NH + 2 * NKV) * ND) + warp * ND;

    float x1[4], x2[4];
#pragma unroll
    for (int i = 0; i < 4; i++) {
        x1[i] = src[lane + 32 * i];
        x2[i] = src[128 + lane + 32 * i];
    }

    if (warp >= 12) { // V: copy
        int kh = warp - 12;
        __half* dst = g_v + ((size_t)(b * NKV + kh) * NS + kvidx[s]) * ND;
#pragma unroll
        for (int i = 0; i < 4; i++) {
            dst[lane + 32 * i]       = __float2half(x1[i]);
            dst[128 + lane + 32 * i] = __float2half(x2[i]);
        }
        return;
    }

    float ss = 0.0f;
#pragma unroll
    for (int i = 0; i < 4; i++) ss += x1[i] * x1[i] + x2[i] * x2[i];
#pragma unroll
    for (int m = 16; m; m >>= 1) ss += __shfl_xor_sync(0xffffffffu, ss, m);
    float inv = rsqrtf(ss * (1.0f / ND) + 1e-6f);

    const float* w   = (warp < 8) ? qw : kw;
    float scale      = (warp < 8) ? 0.0625f : 1.0f; // SCALING folded into q
    __half* dst;
    if (warp < 8) dst = g_q + ((size_t)(b * NH + warp) * NS + s) * ND;
    else          dst = g_k + ((size_t)(b * NKV + (warp - 8)) * NS + kvidx[s]) * ND;

#pragma unroll
    for (int i = 0; i < 4; i++) {
        int d = lane + 32 * i;
        float c  = fcos[(size_t)s * 128 + d];
        float sn = fsin[(size_t)s * 128 + d];
        float y1 = x1[i] * inv * (1.0f + w[d]);
        float y2 = x2[i] * inv * (1.0f + w[d + 128]);
        dst[d]       = __float2half((y1 * c - y2 * sn) * scale);
        dst[d + 128] = __float2half((y2 * c + y1 * sn) * scale);
    }
}

// ---------------------------------------------------------------------------
// Sliding-window flash attention, fp16 m16n8k16 + ldmatrix (round-10 proven).
// ---------------------------------------------------------------------------
#define QP2 132
#define VTP 36

__global__ __launch_bounds__(256, 1) void attn_mma_kernel()
{
    extern __shared__ unsigned smu[];
    unsigned* Qs = smu;                    // [64][QP2]
    unsigned* Ks = Qs + 64 * QP2;          // [64][QP2]
    unsigned* Vs = Ks + 64 * QP2;          // [64][QP2]
    unsigned* Pp = Vs + 64 * QP2;          // [64][VTP]
    float* pmax = (float*)(Pp + 64 * VTP); // [64][2]
    float* psum = pmax + 128;              // [64][2]
    float* ms   = psum + 128;              // [64]
    float* ls   = ms + 64;
    float* cs   = ls + 64;

    int qt = blockIdx.x, h = blockIdx.y, b = blockIdx.z;
    int q0 = qt * 64;
    int kh = h >> 1;

    const unsigned* Qg = (const unsigned*)(g_q + ((size_t)(b * NH + h) * NS + q0) * ND);
    const unsigned* Kg = (const unsigned*)(g_k + (size_t)(b * NKV + kh) * NS * ND);
    const unsigned* Vg = (const unsigned*)(g_v + (size_t)(b * NKV + kh) * NS * ND);

    int tid  = threadIdx.x;
    int lane = tid & 31;
    int warp = tid >> 5;
    int wr = warp & 3;
    int wc = warp >> 2;
    int fr = lane >> 2;
    int fc = lane & 3;
    int r8 = lane & 7, quad = lane >> 3;

    unsigned qsm = (unsigned)__cvta_generic_to_shared(Qs);
    unsigned ksm = (unsigned)__cvta_generic_to_shared(Ks);
    unsigned vsm = (unsigned)__cvta_generic_to_shared(Vs);
    unsigned psm = (unsigned)__cvta_generic_to_shared(Pp);

    unsigned qOff = qsm + (((16 * wr + (quad & 1) * 8 + r8) * QP2 + (quad >> 1) * 4) << 2);
    unsigned kOff = ksm + (((32 * wc + (quad >> 1) * 8 + r8) * QP2 + (quad & 1) * 4) << 2);
    unsigned pOff = psm + ((((quad & 1) * 8 + r8) * VTP + (quad >> 1) * 4) << 2);
    unsigned vOff = vsm + ((((quad & 1) * 8 + r8) * QP2 + 16 * warp + (quad >> 1) * 4) << 2);

    for (int i = tid; i < 64 * 32; i += 256) {
        int r = i >> 5, c4 = (i & 31) * 4;
        *(uint4*)&Qs[r * QP2 + c4] = *(const uint4*)(Qg + (size_t)r * 128 + c4);
    }
    if (tid < 64) { ms[tid] = -1e30f; ls[tid] = 0.0f; }

    float oacc[16][4];
#pragma unroll
    for (int t = 0; t < 16; t++)
#pragma unroll
        for (int e = 0; e < 4; e++) oacc[t][e] = 0.0f;

    int t0 = qt - 16; if (t0 < 0) t0 = 0;
    int r0 = 16 * wr + fr;

    for (int kt = t0; kt <= qt; kt++) {
        int k0 = kt * 64;
        __syncthreads(); // A

        for (int i = tid; i < 64 * 32; i += 256) {
            int r = i >> 5, c4 = (i & 31) * 4;
            *(uint4*)&Ks[r * QP2 + c4] = *(const uint4*)(Kg + (size_t)(k0 + r) * 128 + c4);
            *(uint4*)&Vs[r * QP2 + c4] = *(const uint4*)(Vg + (size_t)(k0 + r) * 128 + c4);
        }
        __syncthreads(); // B

        float sacc[4][4];
#pragma unroll
        for (int t = 0; t < 4; t++)
#pragma unroll
            for (int e = 0; e < 4; e++) sacc[t][e] = 0.0f;

#pragma unroll
        for (int ks = 0; ks < 16; ks++) {
            unsigned kb = ks * 32;
            unsigned a0, a1, a2, a3;
            ldsm4(a0, a1, a2, a3, qOff + kb);
            unsigned bf[4][2];
            ldsm4(bf[0][0], bf[0][1], bf[1][0], bf[1][1], kOff + kb);
            ldsm4(bf[2][0], bf[2][1], bf[3][0], bf[3][1], kOff + 16 * QP2 * 4 + kb);
#pragma unroll
            for (int nt = 0; nt < 4; nt++)
                mma_f16(sacc[nt], a0, a1, a2, a3, bf[nt][0], bf[nt][1]);
        }

        float mx0 = -1e30f, mx1 = -1e30f;
#pragma unroll
        for (int nt = 0; nt < 4; nt++) {
#pragma unroll
            for (int e = 0; e < 4; e++) {
                int r  = r0 + (e >> 1) * 8;
                int kj = k0 + 32 * wc + 8 * nt + 2 * fc + (e & 1);
                int qi = q0 + r;
                float ev = __expf(sacc[nt][e] * 0.04f);
                float v = 50.0f - 100.0f / (ev + 1.0f);
                bool ok = (kj <= qi) && (qi - kj < NWIN);
                v = ok ? v : -1e30f;
                sacc[nt][e] = v;
                if ((e >> 1) == 0) mx0 = fmaxf(mx0, v); else mx1 = fmaxf(mx1, v);
            }
        }
        mx0 = fmaxf(mx0, __shfl_xor_sync(0xffffffffu, mx0, 1));
        mx0 = fmaxf(mx0, __shfl_xor_sync(0xffffffffu, mx0, 2));
        mx1 = fmaxf(mx1, __shfl_xor_sync(0xffffffffu, mx1, 1));
        mx1 = fmaxf(mx1, __shfl_xor_sync(0xffffffffu, mx1, 2));
        if (fc == 0) {
            pmax[r0 * 2 + wc]       = mx0;
            pmax[(r0 + 8) * 2 + wc] = mx1;
        }
        __syncthreads(); // C

        {
            float mo0 = ms[r0];
            float mo1 = ms[r0 + 8];
            float mn0 = fmaxf(mo0, fmaxf(pmax[r0 * 2], pmax[r0 * 2 + 1]));
            float mn1 = fmaxf(mo1, fmaxf(pmax[(r0 + 8) * 2], pmax[(r0 + 8) * 2 + 1]));
            if (wc == 0 && fc == 0) {
                cs[r0]     = __expf(mo0 - mn0);
                cs[r0 + 8] = __expf(mo1 - mn1);
                ms[r0]     = mn0;
                ms[r0 + 8] = mn1;
            }
            float rs0 = 0.0f, rs1 = 0.0f;
#pragma unroll
            for (int nt = 0; nt < 4; nt++) {
                float p0 = __expf(sacc[nt][0] - mn0);
                float p1 = __expf(sacc[nt][1] - mn0);
                float p2 = __expf(sacc[nt][2] - mn1);
                float p3 = __expf(sacc[nt][3] - mn1);
                rs0 += p0 + p1; rs1 += p2 + p3;
                int cu = 16 * wc + 4 * nt + fc;
                Pp[r0 * VTP + cu]       = h2u(p0, p1);
                Pp[(r0 + 8) * VTP + cu] = h2u(p2, p3);
            }
            rs0 += __shfl_xor_sync(0xffffffffu, rs0, 1);
            rs0 += __shfl_xor_sync(0xffffffffu, rs0, 2);
            rs1 += __shfl_xor_sync(0xffffffffu, rs1, 1);
            rs1 += __shfl_xor_sync(0xffffffffu, rs1, 2);
            if (fc == 0) {
                psum[r0 * 2 + wc]       = rs0;
                psum[(r0 + 8) * 2 + wc] = rs1;
            }
        }
        __syncthreads(); // D

        if (tid < 64)
            ls[tid] = ls[tid] * cs[tid] + psum[tid * 2] + psum[tid * 2 + 1];
        {
            float cr0[4], cr1[4];
#pragma unroll
            for (int mt = 0; mt < 4; mt++) {
                cr0[mt] = cs[16 * mt + fr];
                cr1[mt] = cs[16 * mt + fr + 8];
            }
#pragma unroll
            for (int mt = 0; mt < 4; mt++)
#pragma unroll
                for (int nt = 0; nt < 4; nt++) {
                    float* d = oacc[mt * 4 + nt];
                    d[0] *= cr0[mt]; d[1] *= cr0[mt];
                    d[2] *= cr1[mt]; d[3] *= cr1[mt];
                }
#pragma unroll
            for (int s = 0; s < 4; s++) {
                unsigned pa[4][4];
#pragma unroll
                for (int mt = 0; mt < 4; mt++)
                    ldsm4(pa[mt][0], pa[mt][1], pa[mt][2], pa[mt][3],
                          pOff + mt * (16 * VTP * 4) + s * 32);
                unsigned vb[4][2];
                ldsm4t(vb[0][0], vb[0][1], vb[1][0], vb[1][1],
                       vOff + s * (16 * QP2 * 4));
                ldsm4t(vb[2][0], vb[2][1], vb[3][0], vb[3][1],
                       vOff + s * (16 * QP2 * 4) + 32);
#pragma unroll
                for (int mt = 0; mt < 4; mt++)
#pragma unroll
                    for (int nt = 0; nt < 4; nt++)
                        mma_f16(oacc[mt * 4 + nt], pa[mt][0], pa[mt][1], pa[mt][2], pa[mt][3],
                                vb[nt][0], vb[nt][1]);
            }
        }
    }
    __syncthreads();

    {
        unsigned* Og = (unsigned*)(g_att + ((size_t)b * NS + q0) * (NH * ND) + h * ND);
#pragma unroll
        for (int mt = 0; mt < 4; mt++) {
            int r = 16 * mt + fr;
            float il0 = 1.0f / ls[r];
            float il1 = 1.0f / ls[r + 8];
#pragma unroll
            for (int nt = 0; nt < 4; nt++) {
                float* d = oacc[mt * 4 + nt];
                int cu = 16 * warp + 4 * nt + fc;
                Og[(size_t)r * 1024 + cu]       = h2u(d[0] * il0, d[1] * il0);
                Og[(size_t)(r + 8) * 1024 + cu] = h2u(d[2] * il1, d[3] * il1);
            }
        }
    }
}

// ---------------------------------------------------------------------------
extern "C" void kernel_launch(void* const* d_in, const int* in_sizes, int n_in,
                              void* d_out, int out_size)
{
    const float* hidden = (const float*)d_in[0];
    const float* fcos   = (const float*)d_in[1];
    const float* fsin   = (const float*)d_in[2];
    const int*   kvidx  = (const int*)  d_in[3];
    const float* w_qkv  = (const float*)d_in[8];
    const float* w_o    = (const float*)d_in[9];
    const float* qnw    = (const float*)d_in[10];
    const float* knw    = (const float*)d_in[11];
    float* out = (float*)d_out;

    void* p;
    cudaGetSymbolAddress(&p, g_qkv); float*  qkv_ptr = (float*)p;
    cudaGetSymbolAddress(&p, g_att); __half* att_ptr = (__half*)p;
    cudaGetSymbolAddress(&p, g_hh);  __half* hh_ptr  = (__half*)p;
    cudaGetSymbolAddress(&p, g_wq);  __half* wq_ptr  = (__half*)p;
    cudaGetSymbolAddress(&p, g_wo);  __half* wo_ptr  = (__half*)p;

    // 0) convert hidden + weights to fp16
    {
        int n4h = NB * NS * NE / 4;
        f2h_kernel<<<(n4h + 255) / 256, 256>>>(hidden, hh_ptr, n4h);
        int n4q = (NH + 2 * NKV) * ND * NE / 4;
        f2h_kernel<<<(n4q + 255) / 256, 256>>>(w_qkv, wq_ptr, n4q);
        int n4o = NE * NH * ND / 4;
        f2h_kernel<<<(n4o + 255) / 256, 256>>>(w_o, wo_ptr, n4o);
    }

    size_t gsmem = (size_t)4 * ABUF * 4; // 2 buffers x (A+B) = 72 KB
    cudaFuncSetAttribute(hgemm_nt,
                         cudaFuncAttributeMaxDynamicSharedMemorySize,
                         (int)gsmem);

    // 1) QKV projection (pure fp16, cp.async double-buffered, 2 blocks/SM)
    {
        dim3 grid((NH + 2 * NKV) * ND / 128, NB * NS / 128);
        hgemm_nt<<<grid, 256, gsmem>>>(hh_ptr, wq_ptr, qkv_ptr,
                                       NB * NS, (NH + 2 * NKV) * ND, NE);
    }

    // 2) RMSNorm + RoPE + cache scatter (fp16 outputs)
    norm_rope_kernel<<<NB * NS, 512>>>(fcos, fsin, kvidx, qnw, knw);

    // 3) sliding-window flash attention (fp16 m16n8k16 + ldmatrix)
    {
        size_t smem = (size_t)(3 * 64 * QP2 + 64 * VTP + 448) * 4;
        cudaFuncSetAttribute(attn_mma_kernel,
                             cudaFuncAttributeMaxDynamicSharedMemorySize,
                             (int)smem);
        dim3 grid(NS / 64, NH, NB);
        attn_mma_kernel<<<grid, 256, smem>>>();
    }

    // 4) output projection (pure fp16)
    {
        dim3 grid(NE / 128, NB * NS / 128);
        hgemm_nt<<<grid, 256, gsmem>>>(att_ptr, wo_ptr, out, NB * NS, NE, NH * ND);
    }
}

// round 12
// speedup vs baseline: 2.9650x; 1.1070x over previous
#include <cuda_runtime.h>
#include <cuda_fp16.h>
#include <math.h>

#define NB   2
#define NS   4096
#define NE   2560
#define NH   8
#define NKV  4
#define ND   256
#define NWIN 1024

// ---------------- scratch (device globals: allocation-free) ----------------
static __device__ float  g_qkv[(size_t)NB * NS * (NH + 2 * NKV) * ND]; // f32
static __device__ __half g_q  [(size_t)NB * NH  * NS * ND];            // fp16
static __device__ __half g_k  [(size_t)NB * NKV * NS * ND];
static __device__ __half g_v  [(size_t)NB * NKV * NS * ND];
static __device__ __half g_att[(size_t)NB * NS * NH * ND];             // fp16
static __device__ __half g_hh [(size_t)NB * NS * NE];                  // hidden fp16
static __device__ __half g_wq [(size_t)(NH + 2 * NKV) * ND * NE];      // w_qkv fp16
static __device__ __half g_wo [(size_t)NE * NH * ND];                  // w_o fp16

__device__ __forceinline__ unsigned h2u(float x, float y) {
    __half2 h = __floats2half2_rn(x, y);
    return *reinterpret_cast<unsigned*>(&h);
}

__device__ __forceinline__ void mma_f16(float* d,
        unsigned a0, unsigned a1, unsigned a2, unsigned a3,
        unsigned b0, unsigned b1) {
    asm volatile(
        "mma.sync.aligned.m16n8k16.row.col.f32.f16.f16.f32 "
        "{%0,%1,%2,%3},{%4,%5,%6,%7},{%8,%9},{%0,%1,%2,%3};"
        : "+f"(d[0]), "+f"(d[1]), "+f"(d[2]), "+f"(d[3])
        : "r"(a0), "r"(a1), "r"(a2), "r"(a3), "r"(b0), "r"(b1));
}

__device__ __forceinline__ void ldsm4(unsigned& r0, unsigned& r1,
                                      unsigned& r2, unsigned& r3, unsigned a) {
    asm volatile("ldmatrix.sync.aligned.m8n8.x4.shared.b16 {%0,%1,%2,%3}, [%4];"
                 : "=r"(r0), "=r"(r1), "=r"(r2), "=r"(r3) : "r"(a));
}
__device__ __forceinline__ void ldsm4t(unsigned& r0, unsigned& r1,
                                       unsigned& r2, unsigned& r3, unsigned a) {
    asm volatile("ldmatrix.sync.aligned.m8n8.x4.trans.shared.b16 {%0,%1,%2,%3}, [%4];"
                 : "=r"(r0), "=r"(r1), "=r"(r2), "=r"(r3) : "r"(a));
}
__device__ __forceinline__ void cp16(unsigned smem_addr, const void* gptr) {
    asm volatile("cp.async.cg.shared.global [%0], [%1], 16;"
                 :: "r"(smem_addr), "l"(gptr));
}

// ---------------------------------------------------------------------------
// f32 -> f16 bulk convert (float4 granularity)
// ---------------------------------------------------------------------------
__global__ __launch_bounds__(256) void f2h_kernel(
        const float* __restrict__ s, __half* __restrict__ d, int n4)
{
    int i = blockIdx.x * blockDim.x + threadIdx.x;
    if (i < n4) {
        float4 v = ((const float4*)s)[i];
        uint2 u;
        u.x = h2u(v.x, v.y);
        u.y = h2u(v.z, v.w);
        ((uint2*)d)[i] = u;
    }
}

// ---------------------------------------------------------------------------
// Pure-fp16 tensor GEMM: C[M,N] = A[M,K] @ B[N,K]^T, both operands fp16.
// 128x128 tile, BK=64, 256 threads (8 warps, 64x32), m16n8k16 + ldmatrix,
// cp.async double-buffered smem, 2 blocks/SM.  (round-11 proven, unchanged)
// ---------------------------------------------------------------------------
#define GP 36                 // smem pitch in uints; 36 % 32 == 4
#define ABUF (128 * GP)       // one buffer (uints)

__global__ __launch_bounds__(256, 2) void hgemm_nt(
        const __half* __restrict__ A, const __half* __restrict__ Bm,
        float* __restrict__ C, int M, int N, int K)
{
    extern __shared__ unsigned gsm[];
    unsigned* As = gsm;              // [2][ABUF]
    unsigned* Bs = gsm + 2 * ABUF;   // [2][ABUF]

    int tid  = threadIdx.x;
    int lane = tid & 31;
    int warp = tid >> 5;
    int wm = (warp & 1) * 64;
    int wn = (warp >> 1) * 32;

    const __half* Ab = A  + (size_t)blockIdx.y * 128 * K;
    const __half* Bb = Bm + (size_t)blockIdx.x * 128 * K;

    int lrow = tid >> 3;
    int lch  = tid & 7;
    unsigned asmb = (unsigned)__cvta_generic_to_shared(As);
    unsigned bsmb = (unsigned)__cvta_generic_to_shared(Bs);
    unsigned aSt = asmb + ((lrow * GP + lch * 4) << 2);
    unsigned bSt = bsmb + ((lrow * GP + lch * 4) << 2);

    float acc[16][4];
#pragma unroll
    for (int t = 0; t < 16; t++)
#pragma unroll
        for (int e = 0; e < 4; e++) acc[t][e] = 0.0f;

    int fr = lane >> 2;
    int r8 = lane & 7, quad = lane >> 3;
    unsigned aOff = asmb + (((wm + (quad & 1) * 8 + r8) * GP + (quad >> 1) * 4) << 2);
    unsigned bOff = bsmb + (((wn + (quad >> 1) * 8 + r8) * GP + (quad & 1) * 4) << 2);

    int nIter = K >> 6;

#pragma unroll
    for (int i = 0; i < 4; i++) {
        size_t go = (size_t)(lrow + 32 * i) * K + lch * 8;
        cp16(aSt + i * (32 * GP * 4), Ab + go);
        cp16(bSt + i * (32 * GP * 4), Bb + go);
    }
    asm volatile("cp.async.commit_group;");

    for (int it = 0; it < nIter; it++) {
        int buf = it & 1;
        if (it + 1 < nIter) {
            unsigned sb = (buf ^ 1) * (ABUF * 4);
            int k0n = (it + 1) << 6;
#pragma unroll
            for (int i = 0; i < 4; i++) {
                size_t go = (size_t)(lrow + 32 * i) * K + k0n + lch * 8;
                cp16(aSt + sb + i * (32 * GP * 4), Ab + go);
                cp16(bSt + sb + i * (32 * GP * 4), Bb + go);
            }
            asm volatile("cp.async.commit_group;");
            asm volatile("cp.async.wait_group 1;");
        } else {
            asm volatile("cp.async.wait_group 0;");
        }
        __syncthreads();

        unsigned bufo = buf * (ABUF * 4);
#pragma unroll
        for (int ks = 0; ks < 4; ks++) {
            unsigned kb = bufo + ks * 32;
            unsigned af[4][4], bf[4][2];
#pragma unroll
            for (int i = 0; i < 4; i++)
                ldsm4(af[i][0], af[i][1], af[i][2], af[i][3],
                      aOff + i * (16 * GP * 4) + kb);
            ldsm4(bf[0][0], bf[0][1], bf[1][0], bf[1][1], bOff + kb);
            ldsm4(bf[2][0], bf[2][1], bf[3][0], bf[3][1], bOff + 16 * GP * 4 + kb);
#pragma unroll
            for (int i = 0; i < 4; i++)
#pragma unroll
                for (int j = 0; j < 4; j++)
                    mma_f16(acc[i * 4 + j], af[i][0], af[i][1], af[i][2], af[i][3],
                            bf[j][0], bf[j][1]);
        }
        __syncthreads();
    }

    int c2 = (lane & 3) * 2;
#pragma unroll
    for (int i = 0; i < 4; i++) {
        size_t row0 = (size_t)blockIdx.y * 128 + wm + i * 16 + fr;
#pragma unroll
        for (int j = 0; j < 4; j++) {
            float* d = acc[i * 4 + j];
            size_t col = (size_t)blockIdx.x * 128 + wn + j * 8 + c2;
            *(float2*)&C[row0 * N + col]       = make_float2(d[0], d[1]);
            *(float2*)&C[(row0 + 8) * N + col] = make_float2(d[2], d[3]);
        }
    }
}

// ---------------------------------------------------------------------------
// RMSNorm + RoPE + scatter into fp16 q/k/v buffers.
// ---------------------------------------------------------------------------
__global__ __launch_bounds__(512) void norm_rope_kernel(
        const float* __restrict__ fcos, const float* __restrict__ fsin,
        const int*   __restrict__ kvidx,
        const float* __restrict__ qw, const float* __restrict__ kw)
{
    int token = blockIdx.x;
    int b = token / NS;
    int s = token - b * NS;
    int warp = threadIdx.x >> 5;
    int lane = threadIdx.x & 31;

    const float* src = g_qkv + (size_t)token * ((NH + 2 * NKV) * ND) + warp * ND;

    float x1[4], x2[4];
#pragma unroll
    for (int i = 0; i < 4; i++) {
        x1[i] = src[lane + 32 * i];
        x2[i] = src[128 + lane + 32 * i];
    }

    if (warp >= 12) { // V: copy
        int kh = warp - 12;
        __half* dst = g_v + ((size_t)(b * NKV + kh) * NS + kvidx[s]) * ND;
#pragma unroll
        for (int i = 0; i < 4; i++) {
            dst[lane + 32 * i]       = __float2half(x1[i]);
            dst[128 + lane + 32 * i] = __float2half(x2[i]);
        }
        return;
    }

    float ss = 0.0f;
#pragma unroll
    for (int i = 0; i < 4; i++) ss += x1[i] * x1[i] + x2[i] * x2[i];
#pragma unroll
    for (int m = 16; m; m >>= 1) ss += __shfl_xor_sync(0xffffffffu, ss, m);
    float inv = rsqrtf(ss * (1.0f / ND) + 1e-6f);

    const float* w   = (warp < 8) ? qw : kw;
    float scale      = (warp < 8) ? 0.0625f : 1.0f; // SCALING folded into q
    __half* dst;
    if (warp < 8) dst = g_q + ((size_t)(b * NH + warp) * NS + s) * ND;
    else          dst = g_k + ((size_t)(b * NKV + (warp - 8)) * NS + kvidx[s]) * ND;

#pragma unroll
    for (int i = 0; i < 4; i++) {
        int d = lane + 32 * i;
        float c  = fcos[(size_t)s * 128 + d];
        float sn = fsin[(size_t)s * 128 + d];
        float y1 = x1[i] * inv * (1.0f + w[d]);
        float y2 = x2[i] * inv * (1.0f + w[d + 128]);
        dst[d]       = __float2half((y1 * c - y2 * sn) * scale);
        dst[d + 128] = __float2half((y2 * c + y1 * sn) * scale);
    }
}

// ---------------------------------------------------------------------------
// Sliding-window flash attention, fp16 m16n8k16 + ldmatrix.
// NOW 2 blocks/SM: 2 x 109.8 KB smem = 219.5 KB <= 228 KB carveout;
// __launch_bounds__(256,2) caps regs at 128 so a second block co-resides
// and fills the sync/load/softmax bubbles (same lever that took the GEMM
// from 42% -> 60% tensor).
// ---------------------------------------------------------------------------
#define QP2 132
#define VTP 36

__global__ __launch_bounds__(256, 2) void attn_mma_kernel()
{
    extern __shared__ unsigned smu[];
    unsigned* Qs = smu;                    // [64][QP2]
    unsigned* Ks = Qs + 64 * QP2;          // [64][QP2]
    unsigned* Vs = Ks + 64 * QP2;          // [64][QP2]
    unsigned* Pp = Vs + 64 * QP2;          // [64][VTP]
    float* pmax = (float*)(Pp + 64 * VTP); // [64][2]
    float* psum = pmax + 128;              // [64][2]
    float* ms   = psum + 128;              // [64]
    float* ls   = ms + 64;
    float* cs   = ls + 64;

    int qt = blockIdx.x, h = blockIdx.y, b = blockIdx.z;
    int q0 = qt * 64;
    int kh = h >> 1;

    const unsigned* Qg = (const unsigned*)(g_q + ((size_t)(b * NH + h) * NS + q0) * ND);
    const unsigned* Kg = (const unsigned*)(g_k + (size_t)(b * NKV + kh) * NS * ND);
    const unsigned* Vg = (const unsigned*)(g_v + (size_t)(b * NKV + kh) * NS * ND);

    int tid  = threadIdx.x;
    int lane = tid & 31;
    int warp = tid >> 5;
    int wr = warp & 3;
    int wc = warp >> 2;
    int fr = lane >> 2;
    int fc = lane & 3;
    int r8 = lane & 7, quad = lane >> 3;

    unsigned qsm = (unsigned)__cvta_generic_to_shared(Qs);
    unsigned ksm = (unsigned)__cvta_generic_to_shared(Ks);
    unsigned vsm = (unsigned)__cvta_generic_to_shared(Vs);
    unsigned psm = (unsigned)__cvta_generic_to_shared(Pp);

    unsigned qOff = qsm + (((16 * wr + (quad & 1) * 8 + r8) * QP2 + (quad >> 1) * 4) << 2);
    unsigned kOff = ksm + (((32 * wc + (quad >> 1) * 8 + r8) * QP2 + (quad & 1) * 4) << 2);
    unsigned pOff = psm + ((((quad & 1) * 8 + r8) * VTP + (quad >> 1) * 4) << 2);
    unsigned vOff = vsm + ((((quad & 1) * 8 + r8) * QP2 + 16 * warp + (quad >> 1) * 4) << 2);

    for (int i = tid; i < 64 * 32; i += 256) {
        int r = i >> 5, c4 = (i & 31) * 4;
        *(uint4*)&Qs[r * QP2 + c4] = *(const uint4*)(Qg + (size_t)r * 128 + c4);
    }
    if (tid < 64) { ms[tid] = -1e30f; ls[tid] = 0.0f; }

    float oacc[16][4];
#pragma unroll
    for (int t = 0; t < 16; t++)
#pragma unroll
        for (int e = 0; e < 4; e++) oacc[t][e] = 0.0f;

    int t0 = qt - 16; if (t0 < 0) t0 = 0;
    int r0 = 16 * wr + fr;

    for (int kt = t0; kt <= qt; kt++) {
        int k0 = kt * 64;
        __syncthreads(); // A

        for (int i = tid; i < 64 * 32; i += 256) {
            int r = i >> 5, c4 = (i & 31) * 4;
            *(uint4*)&Ks[r * QP2 + c4] = *(const uint4*)(Kg + (size_t)(k0 + r) * 128 + c4);
            *(uint4*)&Vs[r * QP2 + c4] = *(const uint4*)(Vg + (size_t)(k0 + r) * 128 + c4);
        }
        __syncthreads(); // B

        float sacc[4][4];
#pragma unroll
        for (int t = 0; t < 4; t++)
#pragma unroll
            for (int e = 0; e < 4; e++) sacc[t][e] = 0.0f;

#pragma unroll
        for (int ks = 0; ks < 16; ks++) {
            unsigned kb = ks * 32;
            unsigned a0, a1, a2, a3;
            ldsm4(a0, a1, a2, a3, qOff + kb);
            unsigned bf[4][2];
            ldsm4(bf[0][0], bf[0][1], bf[1][0], bf[1][1], kOff + kb);
            ldsm4(bf[2][0], bf[2][1], bf[3][0], bf[3][1], kOff + 16 * QP2 * 4 + kb);
#pragma unroll
            for (int nt = 0; nt < 4; nt++)
                mma_f16(sacc[nt], a0, a1, a2, a3, bf[nt][0], bf[nt][1]);
        }

        float mx0 = -1e30f, mx1 = -1e30f;
#pragma unroll
        for (int nt = 0; nt < 4; nt++) {
#pragma unroll
            for (int e = 0; e < 4; e++) {
                int r  = r0 + (e >> 1) * 8;
                int kj = k0 + 32 * wc + 8 * nt + 2 * fc + (e & 1);
                int qi = q0 + r;
                float ev = __expf(sacc[nt][e] * 0.04f);
                float v = 50.0f - 100.0f / (ev + 1.0f);
                bool ok = (kj <= qi) && (qi - kj < NWIN);
                v = ok ? v : -1e30f;
                sacc[nt][e] = v;
                if ((e >> 1) == 0) mx0 = fmaxf(mx0, v); else mx1 = fmaxf(mx1, v);
            }
        }
        mx0 = fmaxf(mx0, __shfl_xor_sync(0xffffffffu, mx0, 1));
        mx0 = fmaxf(mx0, __shfl_xor_sync(0xffffffffu, mx0, 2));
        mx1 = fmaxf(mx1, __shfl_xor_sync(0xffffffffu, mx1, 1));
        mx1 = fmaxf(mx1, __shfl_xor_sync(0xffffffffu, mx1, 2));
        if (fc == 0) {
            pmax[r0 * 2 + wc]       = mx0;
            pmax[(r0 + 8) * 2 + wc] = mx1;
        }
        __syncthreads(); // C

        {
            float mo0 = ms[r0];
            float mo1 = ms[r0 + 8];
            float mn0 = fmaxf(mo0, fmaxf(pmax[r0 * 2], pmax[r0 * 2 + 1]));
            float mn1 = fmaxf(mo1, fmaxf(pmax[(r0 + 8) * 2], pmax[(r0 + 8) * 2 + 1]));
            if (wc == 0 && fc == 0) {
                cs[r0]     = __expf(mo0 - mn0);
                cs[r0 + 8] = __expf(mo1 - mn1);
                ms[r0]     = mn0;
                ms[r0 + 8] = mn1;
            }
            float rs0 = 0.0f, rs1 = 0.0f;
#pragma unroll
            for (int nt = 0; nt < 4; nt++) {
                float p0 = __expf(sacc[nt][0] - mn0);
                float p1 = __expf(sacc[nt][1] - mn0);
                float p2 = __expf(sacc[nt][2] - mn1);
                float p3 = __expf(sacc[nt][3] - mn1);
                rs0 += p0 + p1; rs1 += p2 + p3;
                int cu = 16 * wc + 4 * nt + fc;
                Pp[r0 * VTP + cu]       = h2u(p0, p1);
                Pp[(r0 + 8) * VTP + cu] = h2u(p2, p3);
            }
            rs0 += __shfl_xor_sync(0xffffffffu, rs0, 1);
            rs0 += __shfl_xor_sync(0xffffffffu, rs0, 2);
            rs1 += __shfl_xor_sync(0xffffffffu, rs1, 1);
            rs1 += __shfl_xor_sync(0xffffffffu, rs1, 2);
            if (fc == 0) {
                psum[r0 * 2 + wc]       = rs0;
                psum[(r0 + 8) * 2 + wc] = rs1;
            }
        }
        __syncthreads(); // D

        if (tid < 64)
            ls[tid] = ls[tid] * cs[tid] + psum[tid * 2] + psum[tid * 2 + 1];
        {
            float cr0[4], cr1[4];
#pragma unroll
            for (int mt = 0; mt < 4; mt++) {
                cr0[mt] = cs[16 * mt + fr];
                cr1[mt] = cs[16 * mt + fr + 8];
            }
#pragma unroll
            for (int mt = 0; mt < 4; mt++)
#pragma unroll
                for (int nt = 0; nt < 4; nt++) {
                    float* d = oacc[mt * 4 + nt];
                    d[0] *= cr0[mt]; d[1] *= cr0[mt];
                    d[2] *= cr1[mt]; d[3] *= cr1[mt];
                }
#pragma unroll
            for (int s = 0; s < 4; s++) {
                unsigned pa[4][4];
#pragma unroll
                for (int mt = 0; mt < 4; mt++)
                    ldsm4(pa[mt][0], pa[mt][1], pa[mt][2], pa[mt][3],
                          pOff + mt * (16 * VTP * 4) + s * 32);
                unsigned vb[4][2];
                ldsm4t(vb[0][0], vb[0][1], vb[1][0], vb[1][1],
                       vOff + s * (16 * QP2 * 4));
                ldsm4t(vb[2][0], vb[2][1], vb[3][0], vb[3][1],
                       vOff + s * (16 * QP2 * 4) + 32);
#pragma unroll
                for (int mt = 0; mt < 4; mt++)
#pragma unroll
                    for (int nt = 0; nt < 4; nt++)
                        mma_f16(oacc[mt * 4 + nt], pa[mt][0], pa[mt][1], pa[mt][2], pa[mt][3],
                                vb[nt][0], vb[nt][1]);
            }
        }
    }
    __syncthreads();

    {
        unsigned* Og = (unsigned*)(g_att + ((size_t)b * NS + q0) * (NH * ND) + h * ND);
#pragma unroll
        for (int mt = 0; mt < 4; mt++) {
            int r = 16 * mt + fr;
            float il0 = 1.0f / ls[r];
            float il1 = 1.0f / ls[r + 8];
#pragma unroll
            for (int nt = 0; nt < 4; nt++) {
                float* d = oacc[mt * 4 + nt];
                int cu = 16 * warp + 4 * nt + fc;
                Og[(size_t)r * 1024 + cu]       = h2u(d[0] * il0, d[1] * il0);
                Og[(size_t)(r + 8) * 1024 + cu] = h2u(d[2] * il1, d[3] * il1);
            }
        }
    }
}

// ---------------------------------------------------------------------------
extern "C" void kernel_launch(void* const* d_in, const int* in_sizes, int n_in,
                              void* d_out, int out_size)
{
    const float* hidden = (const float*)d_in[0];
    const float* fcos   = (const float*)d_in[1];
    const float* fsin   = (const float*)d_in[2];
    const int*   kvidx  = (const int*)  d_in[3];
    const float* w_qkv  = (const float*)d_in[8];
    const float* w_o    = (const float*)d_in[9];
    const float* qnw    = (const float*)d_in[10];
    const float* knw    = (const float*)d_in[11];
    float* out = (float*)d_out;

    void* p;
    cudaGetSymbolAddress(&p, g_qkv); float*  qkv_ptr = (float*)p;
    cudaGetSymbolAddress(&p, g_att); __half* att_ptr = (__half*)p;
    cudaGetSymbolAddress(&p, g_hh);  __half* hh_ptr  = (__half*)p;
    cudaGetSymbolAddress(&p, g_wq);  __half* wq_ptr  = (__half*)p;
    cudaGetSymbolAddress(&p, g_wo);  __half* wo_ptr  = (__half*)p;

    // 0) convert hidden + weights to fp16
    {
        int n4h = NB * NS * NE / 4;
        f2h_kernel<<<(n4h + 255) / 256, 256>>>(hidden, hh_ptr, n4h);
        int n4q = (NH + 2 * NKV) * ND * NE / 4;
        f2h_kernel<<<(n4q + 255) / 256, 256>>>(w_qkv, wq_ptr, n4q);
        int n4o = NE * NH * ND / 4;
        f2h_kernel<<<(n4o + 255) / 256, 256>>>(w_o, wo_ptr, n4o);
    }

    size_t gsmem = (size_t)4 * ABUF * 4; // 72 KB
    cudaFuncSetAttribute(hgemm_nt,
                         cudaFuncAttributeMaxDynamicSharedMemorySize,
                         (int)gsmem);

    // 1) QKV projection (pure fp16, 2 blocks/SM)
    {
        dim3 grid((NH + 2 * NKV) * ND / 128, NB * NS / 128);
        hgemm_nt<<<grid, 256, gsmem>>>(hh_ptr, wq_ptr, qkv_ptr,
                                       NB * NS, (NH + 2 * NKV) * ND, NE);
    }

    // 2) RMSNorm + RoPE + cache scatter (fp16 outputs)
    norm_rope_kernel<<<NB * NS, 512>>>(fcos, fsin, kvidx, qnw, knw);

    // 3) sliding-window flash attention (fp16 + ldmatrix, 2 blocks/SM)
    {
        size_t smem = (size_t)(3 * 64 * QP2 + 64 * VTP + 448) * 4;
        cudaFuncSetAttribute(attn_mma_kernel,
                             cudaFuncAttributeMaxDynamicSharedMemorySize,
                             (int)smem);
        dim3 grid(NS / 64, NH, NB);
        attn_mma_kernel<<<grid, 256, smem>>>();
    }

    // 4) output projection (pure fp16, 2 blocks/SM)
    {
        dim3 grid(NE / 128, NB * NS / 128);
        hgemm_nt<<<grid, 256, gsmem>>>(att_ptr, wo_ptr, out, NB * NS, NE, NH * ND);
    }
}

// round 13
// speedup vs baseline: 3.0142x; 1.0166x over previous
#include <cuda_runtime.h>
#include <cuda_fp16.h>
#include <math.h>

#define NB   2
#define NS   4096
#define NE   2560
#define NH   8
#define NKV  4
#define ND   256
#define NWIN 1024

// ---------------- scratch (device globals: allocation-free) ----------------
static __device__ __half g_qkvh[(size_t)NB * NS * (NH + 2 * NKV) * ND]; // fp16
static __device__ __half g_q  [(size_t)NB * NH  * NS * ND];             // fp16
static __device__ __half g_k  [(size_t)NB * NKV * NS * ND];
static __device__ __half g_v  [(size_t)NB * NKV * NS * ND];
static __device__ __half g_att[(size_t)NB * NS * NH * ND];              // fp16
static __device__ __half g_hh [(size_t)NB * NS * NE];                   // hidden fp16
static __device__ __half g_wq [(size_t)(NH + 2 * NKV) * ND * NE];       // w_qkv fp16
static __device__ __half g_wo [(size_t)NE * NH * ND];                   // w_o fp16

__device__ __forceinline__ unsigned h2u(float x, float y) {
    __half2 h = __floats2half2_rn(x, y);
    return *reinterpret_cast<unsigned*>(&h);
}

__device__ __forceinline__ void mma_f16(float* d,
        unsigned a0, unsigned a1, unsigned a2, unsigned a3,
        unsigned b0, unsigned b1) {
    asm volatile(
        "mma.sync.aligned.m16n8k16.row.col.f32.f16.f16.f32 "
        "{%0,%1,%2,%3},{%4,%5,%6,%7},{%8,%9},{%0,%1,%2,%3};"
        : "+f"(d[0]), "+f"(d[1]), "+f"(d[2]), "+f"(d[3])
        : "r"(a0), "r"(a1), "r"(a2), "r"(a3), "r"(b0), "r"(b1));
}

__device__ __forceinline__ void ldsm4(unsigned& r0, unsigned& r1,
                                      unsigned& r2, unsigned& r3, unsigned a) {
    asm volatile("ldmatrix.sync.aligned.m8n8.x4.shared.b16 {%0,%1,%2,%3}, [%4];"
                 : "=r"(r0), "=r"(r1), "=r"(r2), "=r"(r3) : "r"(a));
}
__device__ __forceinline__ void ldsm4t(unsigned& r0, unsigned& r1,
                                       unsigned& r2, unsigned& r3, unsigned a) {
    asm volatile("ldmatrix.sync.aligned.m8n8.x4.trans.shared.b16 {%0,%1,%2,%3}, [%4];"
                 : "=r"(r0), "=r"(r1), "=r"(r2), "=r"(r3) : "r"(a));
}
__device__ __forceinline__ void cp16(unsigned smem_addr, const void* gptr) {
    asm volatile("cp.async.cg.shared.global [%0], [%1], 16;"
                 :: "r"(smem_addr), "l"(gptr));
}

// ---------------------------------------------------------------------------
// f32 -> f16 bulk convert (float4 granularity)
// ---------------------------------------------------------------------------
__global__ __launch_bounds__(256) void f2h_kernel(
        const float* __restrict__ s, __half* __restrict__ d, int n4)
{
    int i = blockIdx.x * blockDim.x + threadIdx.x;
    if (i < n4) {
        float4 v = ((const float4*)s)[i];
        uint2 u;
        u.x = h2u(v.x, v.y);
        u.y = h2u(v.z, v.w);
        ((uint2*)d)[i] = u;
    }
}

// ---------------------------------------------------------------------------
// Pure-fp16 tensor GEMM: C[M,N] = A[M,K] @ B[N,K]^T, operands fp16.
// 128x128 tile, BK=64, 256 threads (8 warps, 64x32), m16n8k16 + ldmatrix,
// 3-stage cp.async pipeline (ONE barrier per iter), 2 blocks/SM.
// Output type templated: fp16 (QKV) or f32 (final).
// ---------------------------------------------------------------------------
#define GP 36                 // smem pitch in uints; 36 % 32 == 4
#define ABUF (128 * GP)       // one operand buffer (uints)
#define STG  (2 * ABUF)       // one stage (A+B) in uints

template<typename TC>
__global__ __launch_bounds__(256, 2) void hgemm_nt(
        const __half* __restrict__ A, const __half* __restrict__ Bm,
        TC* __restrict__ C, int M, int N, int K)
{
    extern __shared__ unsigned gsm[];   // [3][STG]

    int tid  = threadIdx.x;
    int lane = tid & 31;
    int warp = tid >> 5;
    int wm = (warp & 1) * 64;
    int wn = (warp >> 1) * 32;

    const __half* Ab = A  + (size_t)blockIdx.y * 128 * K;
    const __half* Bb = Bm + (size_t)blockIdx.x * 128 * K;

    int lrow = tid >> 3;
    int lch  = tid & 7;
    unsigned smb = (unsigned)__cvta_generic_to_shared(gsm);
    unsigned aSt = smb + ((lrow * GP + lch * 4) << 2);
    unsigned bSt = aSt + ABUF * 4;

    float acc[16][4];
#pragma unroll
    for (int t = 0; t < 16; t++)
#pragma unroll
        for (int e = 0; e < 4; e++) acc[t][e] = 0.0f;

    int fr = lane >> 2;
    int r8 = lane & 7, quad = lane >> 3;
    unsigned aOff = smb + (((wm + (quad & 1) * 8 + r8) * GP + (quad >> 1) * 4) << 2);
    unsigned bOff = smb + (ABUF << 2)
                  + (((wn + (quad >> 1) * 8 + r8) * GP + (quad & 1) * 4) << 2);

    int nIter = K >> 6;

    // prologue: stages 0 and 1
#pragma unroll
    for (int s = 0; s < 2; s++) {
        unsigned sb = s * (STG * 4);
        int k0 = s << 6;
#pragma unroll
        for (int i = 0; i < 4; i++) {
            size_t go = (size_t)(lrow + 32 * i) * K + k0 + lch * 8;
            cp16(aSt + sb + i * (32 * GP * 4), Ab + go);
            cp16(bSt + sb + i * (32 * GP * 4), Bb + go);
        }
        asm volatile("cp.async.commit_group;");
    }

    for (int it = 0; it < nIter; it++) {
        int buf = it % 3;
        if (it >= nIter - 1) asm volatile("cp.async.wait_group 0;");
        else                 asm volatile("cp.async.wait_group 1;");
        __syncthreads();   // stage `it` visible; slot (it+2)%3 free (read at it-1)

        if (it + 2 < nIter) {
            unsigned sb = ((it + 2) % 3) * (STG * 4);
            int k0n = (it + 2) << 6;
#pragma unroll
            for (int i = 0; i < 4; i++) {
                size_t go = (size_t)(lrow + 32 * i) * K + k0n + lch * 8;
                cp16(aSt + sb + i * (32 * GP * 4), Ab + go);
                cp16(bSt + sb + i * (32 * GP * 4), Bb + go);
            }
            asm volatile("cp.async.commit_group;");
        }

        unsigned bufo = buf * (STG * 4);
#pragma unroll
        for (int ks = 0; ks < 4; ks++) {
            unsigned kb = bufo + ks * 32;
            unsigned af[4][4], bf[4][2];
#pragma unroll
            for (int i = 0; i < 4; i++)
                ldsm4(af[i][0], af[i][1], af[i][2], af[i][3],
                      aOff + i * (16 * GP * 4) + kb);
            ldsm4(bf[0][0], bf[0][1], bf[1][0], bf[1][1], bOff + kb);
            ldsm4(bf[2][0], bf[2][1], bf[3][0], bf[3][1], bOff + 16 * GP * 4 + kb);
#pragma unroll
            for (int i = 0; i < 4; i++)
#pragma unroll
                for (int j = 0; j < 4; j++)
                    mma_f16(acc[i * 4 + j], af[i][0], af[i][1], af[i][2], af[i][3],
                            bf[j][0], bf[j][1]);
        }
    }

    int c2 = (lane & 3) * 2;
#pragma unroll
    for (int i = 0; i < 4; i++) {
        size_t row0 = (size_t)blockIdx.y * 128 + wm + i * 16 + fr;
#pragma unroll
        for (int j = 0; j < 4; j++) {
            float* d = acc[i * 4 + j];
            size_t col = (size_t)blockIdx.x * 128 + wn + j * 8 + c2;
            if (sizeof(TC) == 2) {
                *(unsigned*)&((__half*)C)[row0 * N + col]       = h2u(d[0], d[1]);
                *(unsigned*)&((__half*)C)[(row0 + 8) * N + col] = h2u(d[2], d[3]);
            } else {
                *(float2*)&((float*)C)[row0 * N + col]       = make_float2(d[0], d[1]);
                *(float2*)&((float*)C)[(row0 + 8) * N + col] = make_float2(d[2], d[3]);
            }
        }
    }
}

// ---------------------------------------------------------------------------
// RMSNorm + RoPE + scatter into fp16 q/k/v buffers (reads fp16 qkv).
// ---------------------------------------------------------------------------
__global__ __launch_bounds__(512) void norm_rope_kernel(
        const float* __restrict__ fcos, const float* __restrict__ fsin,
        const int*   __restrict__ kvidx,
        const float* __restrict__ qw, const float* __restrict__ kw)
{
    int token = blockIdx.x;
    int b = token / NS;
    int s = token - b * NS;
    int warp = threadIdx.x >> 5;
    int lane = threadIdx.x & 31;

    const __half* src = g_qkvh + (size_t)token * ((NH + 2 * NKV) * ND) + warp * ND;

    float x1[4], x2[4];
#pragma unroll
    for (int i = 0; i < 4; i++) {
        x1[i] = __half2float(src[lane + 32 * i]);
        x2[i] = __half2float(src[128 + lane + 32 * i]);
    }

    if (warp >= 12) { // V: copy
        int kh = warp - 12;
        __half* dst = g_v + ((size_t)(b * NKV + kh) * NS + kvidx[s]) * ND;
#pragma unroll
        for (int i = 0; i < 4; i++) {
            dst[lane + 32 * i]       = __float2half(x1[i]);
            dst[128 + lane + 32 * i] = __float2half(x2[i]);
        }
        return;
    }

    float ss = 0.0f;
#pragma unroll
    for (int i = 0; i < 4; i++) ss += x1[i] * x1[i] + x2[i] * x2[i];
#pragma unroll
    for (int m = 16; m; m >>= 1) ss += __shfl_xor_sync(0xffffffffu, ss, m);
    float inv = rsqrtf(ss * (1.0f / ND) + 1e-6f);

    const float* w   = (warp < 8) ? qw : kw;
    float scale      = (warp < 8) ? 0.0625f : 1.0f; // SCALING folded into q
    __half* dst;
    if (warp < 8) dst = g_q + ((size_t)(b * NH + warp) * NS + s) * ND;
    else          dst = g_k + ((size_t)(b * NKV + (warp - 8)) * NS + kvidx[s]) * ND;

#pragma unroll
    for (int i = 0; i < 4; i++) {
        int d = lane + 32 * i;
        float c  = fcos[(size_t)s * 128 + d];
        float sn = fsin[(size_t)s * 128 + d];
        float y1 = x1[i] * inv * (1.0f + w[d]);
        float y2 = x2[i] * inv * (1.0f + w[d + 128]);
        dst[d]       = __float2half((y1 * c - y2 * sn) * scale);
        dst[d + 128] = __float2half((y2 * c + y1 * sn) * scale);
    }
}

// ---------------------------------------------------------------------------
// Sliding-window flash attention, fp16 m16n8k16 + ldmatrix, 2 blocks/SM.
// (round-12 proven, unchanged)
// ---------------------------------------------------------------------------
#define QP2 132
#define VTP 36

__global__ __launch_bounds__(256, 2) void attn_mma_kernel()
{
    extern __shared__ unsigned smu[];
    unsigned* Qs = smu;                    // [64][QP2]
    unsigned* Ks = Qs + 64 * QP2;          // [64][QP2]
    unsigned* Vs = Ks + 64 * QP2;          // [64][QP2]
    unsigned* Pp = Vs + 64 * QP2;          // [64][VTP]
    float* pmax = (float*)(Pp + 64 * VTP); // [64][2]
    float* psum = pmax + 128;              // [64][2]
    float* ms   = psum + 128;              // [64]
    float* ls   = ms + 64;
    float* cs   = ls + 64;

    int qt = blockIdx.x, h = blockIdx.y, b = blockIdx.z;
    int q0 = qt * 64;
    int kh = h >> 1;

    const unsigned* Qg = (const unsigned*)(g_q + ((size_t)(b * NH + h) * NS + q0) * ND);
    const unsigned* Kg = (const unsigned*)(g_k + (size_t)(b * NKV + kh) * NS * ND);
    const unsigned* Vg = (const unsigned*)(g_v + (size_t)(b * NKV + kh) * NS * ND);

    int tid  = threadIdx.x;
    int lane = tid & 31;
    int warp = tid >> 5;
    int wr = warp & 3;
    int wc = warp >> 2;
    int fr = lane >> 2;
    int fc = lane & 3;
    int r8 = lane & 7, quad = lane >> 3;

    unsigned qsm = (unsigned)__cvta_generic_to_shared(Qs);
    unsigned ksm = (unsigned)__cvta_generic_to_shared(Ks);
    unsigned vsm = (unsigned)__cvta_generic_to_shared(Vs);
    unsigned psm = (unsigned)__cvta_generic_to_shared(Pp);

    unsigned qOff = qsm + (((16 * wr + (quad & 1) * 8 + r8) * QP2 + (quad >> 1) * 4) << 2);
    unsigned kOff = ksm + (((32 * wc + (quad >> 1) * 8 + r8) * QP2 + (quad & 1) * 4) << 2);
    unsigned pOff = psm + ((((quad & 1) * 8 + r8) * VTP + (quad >> 1) * 4) << 2);
    unsigned vOff = vsm + ((((quad & 1) * 8 + r8) * QP2 + 16 * warp + (quad >> 1) * 4) << 2);

    for (int i = tid; i < 64 * 32; i += 256) {
        int r = i >> 5, c4 = (i & 31) * 4;
        *(uint4*)&Qs[r * QP2 + c4] = *(const uint4*)(Qg + (size_t)r * 128 + c4);
    }
    if (tid < 64) { ms[tid] = -1e30f; ls[tid] = 0.0f; }

    float oacc[16][4];
#pragma unroll
    for (int t = 0; t < 16; t++)
#pragma unroll
        for (int e = 0; e < 4; e++) oacc[t][e] = 0.0f;

    int t0 = qt - 16; if (t0 < 0) t0 = 0;
    int r0 = 16 * wr + fr;

    for (int kt = t0; kt <= qt; kt++) {
        int k0 = kt * 64;
        __syncthreads(); // A

        for (int i = tid; i < 64 * 32; i += 256) {
            int r = i >> 5, c4 = (i & 31) * 4;
            *(uint4*)&Ks[r * QP2 + c4] = *(const uint4*)(Kg + (size_t)(k0 + r) * 128 + c4);
            *(uint4*)&Vs[r * QP2 + c4] = *(const uint4*)(Vg + (size_t)(k0 + r) * 128 + c4);
        }
        __syncthreads(); // B

        float sacc[4][4];
#pragma unroll
        for (int t = 0; t < 4; t++)
#pragma unroll
            for (int e = 0; e < 4; e++) sacc[t][e] = 0.0f;

#pragma unroll
        for (int ks = 0; ks < 16; ks++) {
            unsigned kb = ks * 32;
            unsigned a0, a1, a2, a3;
            ldsm4(a0, a1, a2, a3, qOff + kb);
            unsigned bf[4][2];
            ldsm4(bf[0][0], bf[0][1], bf[1][0], bf[1][1], kOff + kb);
            ldsm4(bf[2][0], bf[2][1], bf[3][0], bf[3][1], kOff + 16 * QP2 * 4 + kb);
#pragma unroll
            for (int nt = 0; nt < 4; nt++)
                mma_f16(sacc[nt], a0, a1, a2, a3, bf[nt][0], bf[nt][1]);
        }

        float mx0 = -1e30f, mx1 = -1e30f;
#pragma unroll
        for (int nt = 0; nt < 4; nt++) {
#pragma unroll
            for (int e = 0; e < 4; e++) {
                int r  = r0 + (e >> 1) * 8;
                int kj = k0 + 32 * wc + 8 * nt + 2 * fc + (e & 1);
                int qi = q0 + r;
                float ev = __expf(sacc[nt][e] * 0.04f);
                float v = 50.0f - 100.0f / (ev + 1.0f);
                bool ok = (kj <= qi) && (qi - kj < NWIN);
                v = ok ? v : -1e30f;
                sacc[nt][e] = v;
                if ((e >> 1) == 0) mx0 = fmaxf(mx0, v); else mx1 = fmaxf(mx1, v);
            }
        }
        mx0 = fmaxf(mx0, __shfl_xor_sync(0xffffffffu, mx0, 1));
        mx0 = fmaxf(mx0, __shfl_xor_sync(0xffffffffu, mx0, 2));
        mx1 = fmaxf(mx1, __shfl_xor_sync(0xffffffffu, mx1, 1));
        mx1 = fmaxf(mx1, __shfl_xor_sync(0xffffffffu, mx1, 2));
        if (fc == 0) {
            pmax[r0 * 2 + wc]       = mx0;
            pmax[(r0 + 8) * 2 + wc] = mx1;
        }
        __syncthreads(); // C

        {
            float mo0 = ms[r0];
            float mo1 = ms[r0 + 8];
            float mn0 = fmaxf(mo0, fmaxf(pmax[r0 * 2], pmax[r0 * 2 + 1]));
            float mn1 = fmaxf(mo1, fmaxf(pmax[(r0 + 8) * 2], pmax[(r0 + 8) * 2 + 1]));
            if (wc == 0 && fc == 0) {
                cs[r0]     = __expf(mo0 - mn0);
                cs[r0 + 8] = __expf(mo1 - mn1);
                ms[r0]     = mn0;
                ms[r0 + 8] = mn1;
            }
            float rs0 = 0.0f, rs1 = 0.0f;
#pragma unroll
            for (int nt = 0; nt < 4; nt++) {
                float p0 = __expf(sacc[nt][0] - mn0);
                float p1 = __expf(sacc[nt][1] - mn0);
                float p2 = __expf(sacc[nt][2] - mn1);
                float p3 = __expf(sacc[nt][3] - mn1);
                rs0 += p0 + p1; rs1 += p2 + p3;
                int cu = 16 * wc + 4 * nt + fc;
                Pp[r0 * VTP + cu]       = h2u(p0, p1);
                Pp[(r0 + 8) * VTP + cu] = h2u(p2, p3);
            }
            rs0 += __shfl_xor_sync(0xffffffffu, rs0, 1);
            rs0 += __shfl_xor_sync(0xffffffffu, rs0, 2);
            rs1 += __shfl_xor_sync(0xffffffffu, rs1, 1);
            rs1 += __shfl_xor_sync(0xffffffffu, rs1, 2);
            if (fc == 0) {
                psum[r0 * 2 + wc]       = rs0;
                psum[(r0 + 8) * 2 + wc] = rs1;
            }
        }
        __syncthreads(); // D

        if (tid < 64)
            ls[tid] = ls[tid] * cs[tid] + psum[tid * 2] + psum[tid * 2 + 1];
        {
            float cr0[4], cr1[4];
#pragma unroll
            for (int mt = 0; mt < 4; mt++) {
                cr0[mt] = cs[16 * mt + fr];
                cr1[mt] = cs[16 * mt + fr + 8];
            }
#pragma unroll
            for (int mt = 0; mt < 4; mt++)
#pragma unroll
                for (int nt = 0; nt < 4; nt++) {
                    float* d = oacc[mt * 4 + nt];
                    d[0] *= cr0[mt]; d[1] *= cr0[mt];
                    d[2] *= cr1[mt]; d[3] *= cr1[mt];
                }
#pragma unroll
            for (int s = 0; s < 4; s++) {
                unsigned pa[4][4];
#pragma unroll
                for (int mt = 0; mt < 4; mt++)
                    ldsm4(pa[mt][0], pa[mt][1], pa[mt][2], pa[mt][3],
                          pOff + mt * (16 * VTP * 4) + s * 32);
                unsigned vb[4][2];
                ldsm4t(vb[0][0], vb[0][1], vb[1][0], vb[1][1],
                       vOff + s * (16 * QP2 * 4));
                ldsm4t(vb[2][0], vb[2][1], vb[3][0], vb[3][1],
                       vOff + s * (16 * QP2 * 4) + 32);
#pragma unroll
                for (int mt = 0; mt < 4; mt++)
#pragma unroll
                    for (int nt = 0; nt < 4; nt++)
                        mma_f16(oacc[mt * 4 + nt], pa[mt][0], pa[mt][1], pa[mt][2], pa[mt][3],
                                vb[nt][0], vb[nt][1]);
            }
        }
    }
    __syncthreads();

    {
        unsigned* Og = (unsigned*)(g_att + ((size_t)b * NS + q0) * (NH * ND) + h * ND);
#pragma unroll
        for (int mt = 0; mt < 4; mt++) {
            int r = 16 * mt + fr;
            float il0 = 1.0f / ls[r];
            float il1 = 1.0f / ls[r + 8];
#pragma unroll
            for (int nt = 0; nt < 4; nt++) {
                float* d = oacc[mt * 4 + nt];
                int cu = 16 * warp + 4 * nt + fc;
                Og[(size_t)r * 1024 + cu]       = h2u(d[0] * il0, d[1] * il0);
                Og[(size_t)(r + 8) * 1024 + cu] = h2u(d[2] * il1, d[3] * il1);
            }
        }
    }
}

// ---------------------------------------------------------------------------
extern "C" void kernel_launch(void* const* d_in, const int* in_sizes, int n_in,
                              void* d_out, int out_size)
{
    const float* hidden = (const float*)d_in[0];
    const float* fcos   = (const float*)d_in[1];
    const float* fsin   = (const float*)d_in[2];
    const int*   kvidx  = (const int*)  d_in[3];
    const float* w_qkv  = (const float*)d_in[8];
    const float* w_o    = (const float*)d_in[9];
    const float* qnw    = (const float*)d_in[10];
    const float* knw    = (const float*)d_in[11];
    float* out = (float*)d_out;

    void* p;
    cudaGetSymbolAddress(&p, g_qkvh); __half* qkv_ptr = (__half*)p;
    cudaGetSymbolAddress(&p, g_att);  __half* att_ptr = (__half*)p;
    cudaGetSymbolAddress(&p, g_hh);   __half* hh_ptr  = (__half*)p;
    cudaGetSymbolAddress(&p, g_wq);   __half* wq_ptr  = (__half*)p;
    cudaGetSymbolAddress(&p, g_wo);   __half* wo_ptr  = (__half*)p;

    // 0) convert hidden + weights to fp16
    {
        int n4h = NB * NS * NE / 4;
        f2h_kernel<<<(n4h + 255) / 256, 256>>>(hidden, hh_ptr, n4h);
        int n4q = (NH + 2 * NKV) * ND * NE / 4;
        f2h_kernel<<<(n4q + 255) / 256, 256>>>(w_qkv, wq_ptr, n4q);
        int n4o = NE * NH * ND / 4;
        f2h_kernel<<<(n4o + 255) / 256, 256>>>(w_o, wo_ptr, n4o);
    }

    size_t gsmem = (size_t)3 * STG * 4; // 3 stages x (A+B) = 108 KB
    cudaFuncSetAttribute(hgemm_nt<__half>,
                         cudaFuncAttributeMaxDynamicSharedMemorySize, (int)gsmem);
    cudaFuncSetAttribute(hgemm_nt<float>,
                         cudaFuncAttributeMaxDynamicSharedMemorySize, (int)gsmem);

    // 1) QKV projection (fp16 in, fp16 out, 3-stage pipeline, 2 blocks/SM)
    {
        dim3 grid((NH + 2 * NKV) * ND / 128, NB * NS / 128);
        hgemm_nt<__half><<<grid, 256, gsmem>>>(hh_ptr, wq_ptr, qkv_ptr,
                                               NB * NS, (NH + 2 * NKV) * ND, NE);
    }

    // 2) RMSNorm + RoPE + cache scatter (fp16 in/out)
    norm_rope_kernel<<<NB * NS, 512>>>(fcos, fsin, kvidx, qnw, knw);

    // 3) sliding-window flash attention (fp16 + ldmatrix, 2 blocks/SM)
    {
        size_t smem = (size_t)(3 * 64 * QP2 + 64 * VTP + 448) * 4;
        cudaFuncSetAttribute(attn_mma_kernel,
                             cudaFuncAttributeMaxDynamicSharedMemorySize,
                             (int)smem);
        dim3 grid(NS / 64, NH, NB);
        attn_mma_kernel<<<grid, 256, smem>>>();
    }

    // 4) output projection (fp16 in, f32 out)
    {
        dim3 grid(NE / 128, NB * NS / 128);
        hgemm_nt<float><<<grid, 256, gsmem>>>(att_ptr, wo_ptr, out,
                                              NB * NS, NE, NH * ND);
    }
}